// round 8
// baseline (speedup 1.0000x reference)
#include <cuda_runtime.h>
#include <cuda_bf16.h>
#include <math.h>
#include <stdint.h>

// ---------------------------------------------------------------------------
// Problem constants
// ---------------------------------------------------------------------------
#define Nn   16
#define Cc   256
#define Hh   64
#define Ww   64
#define PP   66                       // padded spatial (1 halo each side)
#define NPIX (Cc*Hh*Ww)               // per-sample elements (GroupNorm group)
#define XQTOT (Nn*PP*PP*Cc)           // NHWC padded bf16 activations
#define WTOT (Cc*Cc*9)
#define GN_EPSF 1e-5f

// ---------------------------------------------------------------------------
// Scratch (__device__ globals; no allocation anywhere)
// ---------------------------------------------------------------------------
__device__ __align__(1024) __nv_bfloat16 g_xq[XQTOT];   // [n][ph][pw][ic]
__device__ __align__(1024) __nv_bfloat16 g_wq[WTOT];    // [tap][ic][oc], {-1,0,1}
__device__ double g_sum[Nn];
__device__ double g_sumsq[Nn];
__device__ double g_wabs;
__device__ float g_cmin[Nn*Cc], g_cmax[Nn*Cc];          // per-(n,c) extremes of x
__device__ float g_meanf[Nn], g_istdf[Nn];
__device__ float g_qscale;   // 128 / gamma
__device__ float g_coef;     // 0.01 * gamma / 128
__device__ float g_delta;    // 0.7 * mean|w|

// ---------------------------------------------------------------------------
// Portable PTX helpers (sm_80+ only; must compile under plain sm_100)
// ---------------------------------------------------------------------------
__device__ __forceinline__ uint32_t smem_u32(const void* p) {
    uint32_t a;
    asm("{ .reg .u64 t; cvta.to.shared.u64 t, %1; cvt.u32.u64 %0, t; }" : "=r"(a) : "l"(p));
    return a;
}
__device__ __forceinline__ void cp16(uint32_t dst, const void* src) {
    asm volatile("cp.async.cg.shared.global [%0], [%1], 16;" :: "r"(dst), "l"(src) : "memory");
}
__device__ __forceinline__ void cp_commit() {
    asm volatile("cp.async.commit_group;" ::: "memory");
}
__device__ __forceinline__ void ldsm_x4(uint32_t a, uint32_t& r0, uint32_t& r1,
                                        uint32_t& r2, uint32_t& r3) {
    asm volatile("ldmatrix.sync.aligned.m8n8.x4.shared.b16 {%0,%1,%2,%3}, [%4];"
                 : "=r"(r0), "=r"(r1), "=r"(r2), "=r"(r3) : "r"(a));
}
__device__ __forceinline__ void ldsm_x4t(uint32_t a, uint32_t& r0, uint32_t& r1,
                                         uint32_t& r2, uint32_t& r3) {
    asm volatile("ldmatrix.sync.aligned.m8n8.x4.trans.shared.b16 {%0,%1,%2,%3}, [%4];"
                 : "=r"(r0), "=r"(r1), "=r"(r2), "=r"(r3) : "r"(a));
}
__device__ __forceinline__ void mma16816(float* d, const uint32_t* a,
                                         uint32_t b0, uint32_t b1) {
    asm volatile(
        "mma.sync.aligned.m16n8k16.row.col.f32.bf16.bf16.f32 "
        "{%0,%1,%2,%3}, {%4,%5,%6,%7}, {%8,%9}, {%0,%1,%2,%3};"
        : "+f"(d[0]), "+f"(d[1]), "+f"(d[2]), "+f"(d[3])
        : "r"(a[0]), "r"(a[1]), "r"(a[2]), "r"(a[3]), "r"(b0), "r"(b1));
}

// ---------------------------------------------------------------------------
// K0: zero reduction scratch
// ---------------------------------------------------------------------------
__global__ void k_init() {
    int t = threadIdx.x;
    if (t < Nn) { g_sum[t] = 0.0; g_sumsq[t] = 0.0; }
    if (t == 0) { g_wabs = 0.0; }
}

// ---------------------------------------------------------------------------
// K1: per-sample sum / sumsq + exact per-(n,c) min/max of x.
// Each block covers exactly 4 whole channels (16384 contiguous elems).
// ---------------------------------------------------------------------------
__global__ void k_stats(const float* __restrict__ x) {
    int n = blockIdx.y;
    const float* p = x + (size_t)n * NPIX + (size_t)blockIdx.x * 16384;
    int tid = threadIdx.x;
    float s = 0.f, ss = 0.f;
    float mn[4] = {3.4e38f, 3.4e38f, 3.4e38f, 3.4e38f};
    float mx[4] = {-3.4e38f, -3.4e38f, -3.4e38f, -3.4e38f};
#pragma unroll
    for (int k = 0; k < 16; k++) {
        int ch = k >> 2;                       // constant per unrolled iter
        float4 v = *(const float4*)(p + tid * 4 + k * 1024);
        s  += v.x + v.y + v.z + v.w;
        ss += v.x*v.x + v.y*v.y + v.z*v.z + v.w*v.w;
        mn[ch] = fminf(mn[ch], fminf(fminf(v.x, v.y), fminf(v.z, v.w)));
        mx[ch] = fmaxf(mx[ch], fmaxf(fmaxf(v.x, v.y), fmaxf(v.z, v.w)));
    }
#pragma unroll
    for (int off = 16; off; off >>= 1) {
        s  += __shfl_xor_sync(0xffffffffu, s,  off);
        ss += __shfl_xor_sync(0xffffffffu, ss, off);
#pragma unroll
        for (int j = 0; j < 4; j++) {
            mn[j] = fminf(mn[j], __shfl_xor_sync(0xffffffffu, mn[j], off));
            mx[j] = fmaxf(mx[j], __shfl_xor_sync(0xffffffffu, mx[j], off));
        }
    }
    __shared__ double ws[8], wss[8];
    __shared__ float smn[8][4], smx[8][4];
    int wid = tid >> 5, lane = tid & 31;
    if (lane == 0) {
        ws[wid] = (double)s; wss[wid] = (double)ss;
#pragma unroll
        for (int j = 0; j < 4; j++) { smn[wid][j] = mn[j]; smx[wid][j] = mx[j]; }
    }
    __syncthreads();
    if (tid == 0) {
        double S = 0.0, SS = 0.0;
#pragma unroll
        for (int i = 0; i < 8; i++) { S += ws[i]; SS += wss[i]; }
        atomicAdd(&g_sum[n], S);
        atomicAdd(&g_sumsq[n], SS);
    }
    if (tid < 4) {
        float a = 3.4e38f, bmax = -3.4e38f;
#pragma unroll
        for (int w = 0; w < 8; w++) {
            a = fminf(a, smn[w][tid]);
            bmax = fmaxf(bmax, smx[w][tid]);
        }
        int c = blockIdx.x * 4 + tid;
        g_cmin[n * Cc + c] = a;
        g_cmax[n * Cc + c] = bmax;
    }
}

// ---------------------------------------------------------------------------
// K1w: sum |w|
// ---------------------------------------------------------------------------
__global__ void k_wabs(const float* __restrict__ w) {
    int tid = threadIdx.x;
    float s = 0.f;
    for (int i = blockIdx.x * 256 + tid; i < WTOT; i += gridDim.x * 256)
        s += fabsf(w[i]);
#pragma unroll
    for (int off = 16; off; off >>= 1) s += __shfl_xor_sync(0xffffffffu, s, off);
    __shared__ double ws[8];
    int wid = tid >> 5, lane = tid & 31;
    if (lane == 0) ws[wid] = (double)s;
    __syncthreads();
    if (tid == 0) {
        double S = 0.0;
#pragma unroll
        for (int i = 0; i < 8; i++) S += ws[i];
        atomicAdd(&g_wabs, S);
    }
}

__device__ __forceinline__ void sample_stats(int n, float& fm, float& istd) {
    double S = g_sum[n], SS = g_sumsq[n];
    double m = S * (1.0 / (double)NPIX);
    double v = SS * (1.0 / (double)NPIX) - m * m;
    fm = (float)m;
    istd = 1.0f / sqrtf((float)v + GN_EPSF);
}

// ---------------------------------------------------------------------------
// K2: finalize scalars.  gamma from per-channel endpoints (affine GroupNorm
// is monotone in x per (n,c), so |.| max is at an endpoint; identical fp
// formula applied to actual data values -> bit-identical to elementwise max).
// ---------------------------------------------------------------------------
__global__ void k_post(const float* __restrict__ lnw, const float* __restrict__ lnb) {
    __shared__ float sm[Nn], si[Nn];
    __shared__ float wred[8];
    int tid = threadIdx.x;
    if (tid < Nn) {
        float fm, istd;
        sample_stats(tid, fm, istd);
        g_meanf[tid] = fm; g_istdf[tid] = istd;
        sm[tid] = fm; si[tid] = istd;
    }
    __syncthreads();
    float m = 0.f;
#pragma unroll
    for (int it = 0; it < 16; it++) {
        int idx = it * 256 + tid;
        int n = idx >> 8, c = idx & 255;
        float fm = sm[n], istd = si[n], g = lnw[c], bb = lnb[c];
        m = fmaxf(m, fabsf(((g_cmin[idx] - fm) * istd) * g + bb));
        m = fmaxf(m, fabsf(((g_cmax[idx] - fm) * istd) * g + bb));
    }
#pragma unroll
    for (int off = 16; off; off >>= 1) m = fmaxf(m, __shfl_xor_sync(0xffffffffu, m, off));
    int wid = tid >> 5, lane = tid & 31;
    if (lane == 0) wred[wid] = m;
    __syncthreads();
    if (tid == 0) {
#pragma unroll
        for (int i = 1; i < 8; i++) m = fmaxf(m, wred[i]);
        float gamma = fmaxf(m, 1e-6f);
        g_qscale = 128.0f / gamma;
        g_coef = 0.01f * gamma * (1.0f / 128.0f);
        g_delta = 0.7f * (float)(g_wabs * (1.0 / (double)WTOT));
    }
}

// ---------------------------------------------------------------------------
// K3a: zero the halo of g_xq
// ---------------------------------------------------------------------------
__global__ void k_halo() {
    int idx = blockIdx.x * 256 + threadIdx.x;       // 520 blocks
    int n = idx / (260 * 32);
    int r = idx - n * (260 * 32);
    int p = r >> 5, q = r & 31;
    int ph, pw;
    if (p < 66)       { ph = 0;       pw = p; }
    else if (p < 132) { ph = 65;      pw = p - 66; }
    else if (p < 196) { ph = p - 131; pw = 0; }
    else              { ph = p - 195; pw = 65; }
    uint4 z = make_uint4(0, 0, 0, 0);
    *(uint4*)(g_xq + ((size_t)(n * PP + ph) * PP + pw) * Cc + q * 8) = z;
}

// ---------------------------------------------------------------------------
// K3: quantize + NCHW->NHWC transpose into padded bf16 scratch
// ---------------------------------------------------------------------------
__global__ void k_quant_t(const float* __restrict__ x,
                          const float* __restrict__ lnw,
                          const float* __restrict__ lnb) {
    __shared__ float sm[64][68];
    int b = blockIdx.x;
    int ic4 = b & 3, h = (b >> 2) & 63, n = b >> 8;
    int tid = threadIdx.x;
    float mean = g_meanf[n], istd = g_istdf[n], qs = g_qscale;

    const float* xb = x + ((size_t)n * Cc + ic4 * 64) * 4096 + h * 64;
#pragma unroll
    for (int i = tid; i < 1024; i += 256) {
        int row = i >> 4, c4 = i & 15;
        float4 v = *(const float4*)(xb + (size_t)row * 4096 + c4 * 4);
        *(float4*)&sm[row][c4 * 4] = v;
    }
    __syncthreads();

    __nv_bfloat16* ob = g_xq + ((size_t)(n * PP + h + 1) * PP + 1) * Cc + ic4 * 64;
#pragma unroll
    for (int j = tid; j < 512; j += 256) {
        int p = j >> 3, seg = j & 7;
        unsigned short hv[8];
#pragma unroll
        for (int e = 0; e < 8; e++) {
            int cl = seg * 8 + e;
            int c = ic4 * 64 + cl;
            float v = sm[cl][p];
            float xl = ((v - mean) * istd) * lnw[c] + lnb[c];
            float z = fminf(fmaxf(xl * qs, -128.0f), 128.0f);
            hv[e] = __bfloat16_as_ushort(__float2bfloat16_rn(rintf(z)));
        }
        uint4 u;
        u.x = (uint32_t)hv[0] | ((uint32_t)hv[1] << 16);
        u.y = (uint32_t)hv[2] | ((uint32_t)hv[3] << 16);
        u.z = (uint32_t)hv[4] | ((uint32_t)hv[5] << 16);
        u.w = (uint32_t)hv[6] | ((uint32_t)hv[7] << 16);
        *(uint4*)(ob + (size_t)p * Cc + seg * 8) = u;
    }
}

// ---------------------------------------------------------------------------
// K3w: ternarize weights -> bf16 [tap][ic][oc]
// ---------------------------------------------------------------------------
__global__ void k_wq(const float* __restrict__ w) {
    int idx = blockIdx.x * 256 + threadIdx.x;       // 2304 blocks
    int tap = idx >> 16;
    int rem = idx & 65535;
    int ic = rem >> 8, oc = rem & 255;
    float v = w[(size_t)(oc * Cc + ic) * 9 + tap];
    float d = g_delta;
    float q = (v > d) ? 1.f : ((v < -d) ? -1.f : 0.f);
    g_wq[idx] = __float2bfloat16_rn(q);
}

// ---------------------------------------------------------------------------
// K4: implicit-GEMM conv via mma.sync with kx tap-reuse A strips.
// CTA: 128 px (2 rows x 64 cols) x 128 oc.  24 chunks = ky(3) x ic-chunk(8).
// Per chunk: one 2x66-px A strip (covers kx=0..2) + 3 B tap-tiles.
// 3-stage cp.async ring; 8 warps 2(M) x 4(N); warp 64px x 32oc; 64 accums.
// ---------------------------------------------------------------------------
#define STAGES 3
#define A_BYTES 8448                  // 132 strip-px * 64 B
#define STAGE_B (A_BYTES + 3 * 8192)  // 33024
#define CONV_SMEM (STAGES * STAGE_B)  // 99072; epilogue reuse needs 64KB

__global__ void __launch_bounds__(256, 2)
k_conv(const float* __restrict__ bias, float* __restrict__ out) {
    extern __shared__ __align__(1024) char smem[];
    uint32_t sb = smem_u32(smem);
    float* sbuf = (float*)smem;

    int tid = threadIdx.x, lid = tid & 31, wid = tid >> 5;
    int wm = wid & 1, wn = wid >> 1;              // warp grid 2(M) x 4(N)
    int b = blockIdx.x;
    int ocb = b & 1, rp = (b >> 1) & 31, n = b >> 6;
    int y0 = rp * 2, ocBase = ocb * 128;

    const __nv_bfloat16* xqn = g_xq + (size_t)n * PP * PP * Cc;

    int bk0 = tid >> 4, bc0 = tid & 15;           // B staging coords
    uint32_t bsw = (uint32_t)(bc0 ^ (bk0 & 7)) << 4;

    float d[4][4][4];
#pragma unroll
    for (int i = 0; i < 4; i++)
#pragma unroll
        for (int j = 0; j < 4; j++)
#pragma unroll
            for (int e = 0; e < 4; e++) d[i][j][e] = 0.f;

    auto stage = [&](int ch, int s) {
        if (ch < 24) {
            int ky = ch >> 3, icc = ch & 7;
            int ic0 = icc * 32;
            uint32_t As = sb + s * STAGE_B;
            uint32_t Bs = As + A_BYTES;
            // A strip: 132 px (2 rows x 66 cols) x 32 ic = 528 cp16
#pragma unroll
            for (int rr = 0; rr < 3; rr++) {
                int idx = tid + rr * 256;
                if (rr < 2 || tid < 16) {
                    int px = idx >> 2, c = idx & 3;
                    int row = (px >= 66) ? 1 : 0;
                    int col = px - row * 66;
                    cp16(As + px * 64 + ((c ^ ((px >> 1) & 3)) << 4),
                         xqn + ((size_t)(y0 + ky + row) * PP + col) * Cc + ic0 + c * 8);
                }
            }
            // B: 3 kx taps, each 32 ic x 128 oc (R4-proven layout per tap)
#pragma unroll
            for (int t = 0; t < 3; t++) {
                const __nv_bfloat16* wb =
                    g_wq + (size_t)(ky * 3 + t) * 65536 + (size_t)ic0 * 256 + ocBase + bc0 * 8;
                uint32_t Bt = Bs + t * 8192;
                cp16(Bt + bk0 * 256 + bsw, wb + (size_t)bk0 * 256);
                cp16(Bt + (bk0 + 16) * 256 + bsw, wb + (size_t)(bk0 + 16) * 256);
            }
        }
        cp_commit();
    };

    stage(0, 0); stage(1, 1);

    int sc = 0, sp = 2;                            // consume slot, produce slot
    for (int it = 0; it < 24; it++) {
        __syncthreads();
        stage(it + 2, sp);
        asm volatile("cp.async.wait_group 2;" ::: "memory");
        __syncthreads();

        uint32_t As = sb + sc * STAGE_B;
        uint32_t Bs = As + A_BYTES;
#pragma unroll
        for (int kx = 0; kx < 3; kx++) {
            uint32_t Bt = Bs + kx * 8192;
#pragma unroll
            for (int g = 0; g < 2; g++) {
                uint32_t a[4][4];
#pragma unroll
                for (int i = 0; i < 4; i++) {
                    int px = wm * 64 + i * 16 + (lid & 15);
                    int pxs = (px >> 6) * 66 + (px & 63) + kx;
                    int kb = g * 2 + (lid >> 4);
                    int ph = kb ^ ((pxs >> 1) & 3);
                    ldsm_x4(As + pxs * 64 + ph * 16, a[i][0], a[i][1], a[i][2], a[i][3]);
                }
#pragma unroll
                for (int jj = 0; jj < 2; jj++) {
                    uint32_t bf[4];
                    int k = g * 16 + (lid & 15);
                    int cb = wn * 4 + jj * 2 + (lid >> 4);
                    int ph = cb ^ (k & 7);
                    ldsm_x4t(Bt + k * 256 + ph * 16, bf[0], bf[1], bf[2], bf[3]);
#pragma unroll
                    for (int i = 0; i < 4; i++) {
                        mma16816(d[i][jj * 2], a[i], bf[0], bf[1]);
                        mma16816(d[i][jj * 2 + 1], a[i], bf[2], bf[3]);
                    }
                }
            }
        }
        if (++sc == 3) sc = 0;
        if (++sp == 3) sp = 0;
    }
    asm volatile("cp.async.wait_group 0;" ::: "memory");
    __syncthreads();

    // ---- epilogue: per-warp smem transpose -> coalesced NCHW float4 stores ----
    int wb = wid * 2048;                           // 8KB float region per warp
    int q = lid >> 2, t2 = (lid & 3) * 2;
#pragma unroll
    for (int i = 0; i < 4; i++) {
#pragma unroll
        for (int j = 0; j < 4; j++) {
            int px = i * 16 + q;
            int oc = j * 8 + t2;
            sbuf[wb + oc * 64 + px]           = d[i][j][0];
            sbuf[wb + (oc + 1) * 64 + px]     = d[i][j][1];
            sbuf[wb + oc * 64 + px + 8]       = d[i][j][2];
            sbuf[wb + (oc + 1) * 64 + px + 8] = d[i][j][3];
        }
    }
    __syncwarp();
    float coef = g_coef;
    int y = y0 + wm;
#pragma unroll
    for (int itr = 0; itr < 16; itr++) {
        int ocl = itr * 2 + (lid >> 4);
        int x4 = (lid & 15) * 4;
        float4 v = *(float4*)&sbuf[wb + ocl * 64 + x4];
        int oc = ocBase + wn * 32 + ocl;
        float bz = bias[oc];
        v.x = v.x * coef + bz;
        v.y = v.y * coef + bz;
        v.z = v.z * coef + bz;
        v.w = v.w * coef + bz;
        *(float4*)(out + (((size_t)n * Cc + oc) * Hh + y) * Ww + x4) = v;
    }
}

// ---------------------------------------------------------------------------
// Host launch
// ---------------------------------------------------------------------------
extern "C" void kernel_launch(void* const* d_in, const int* in_sizes, int n_in,
                              void* d_out, int out_size) {
    const float* x    = (const float*)d_in[0];
    const float* w    = (const float*)d_in[1];
    const float* bias = (const float*)d_in[2];
    const float* lnw  = (const float*)d_in[3];
    const float* lnb  = (const float*)d_in[4];
    float* out = (float*)d_out;

    cudaFuncSetAttribute(k_conv, cudaFuncAttributeMaxDynamicSharedMemorySize, CONV_SMEM);

    k_init<<<1, 32>>>();
    k_stats<<<dim3(64, Nn), 256>>>(x);
    k_wabs<<<64, 256>>>(w);
    k_post<<<1, 256>>>(lnw, lnb);
    k_halo<<<520, 256>>>();
    k_quant_t<<<4096, 256>>>(x, lnw, lnb);
    k_wq<<<2304, 256>>>(w);
    k_conv<<<1024, 256, CONV_SMEM>>>(bias, out);
}

// round 9
// speedup vs baseline: 1.0071x; 1.0071x over previous
#include <cuda_runtime.h>
#include <cuda_bf16.h>
#include <math.h>
#include <stdint.h>

// ---------------------------------------------------------------------------
// Problem constants
// ---------------------------------------------------------------------------
#define Nn   16
#define Cc   256
#define Hh   64
#define Ww   64
#define PP   66                       // padded spatial (1 halo each side)
#define NPIX (Cc*Hh*Ww)               // per-sample elements (GroupNorm group)
#define XQTOT (Nn*PP*PP*Cc)           // NHWC padded bf16 activations
#define WTOT (Cc*Cc*9)
#define GN_EPSF 1e-5f

// ---------------------------------------------------------------------------
// Scratch (__device__ globals; no allocation anywhere)
// ---------------------------------------------------------------------------
__device__ __align__(1024) __nv_bfloat16 g_xq[XQTOT];   // [n][ph][pw][ic]
__device__ __align__(1024) __nv_bfloat16 g_wq[WTOT];    // [tap][ic][oc], {-1,0,1}
__device__ double g_sum[Nn];
__device__ double g_sumsq[Nn];
__device__ double g_wabs;
__device__ float g_cmin[Nn*Cc], g_cmax[Nn*Cc];          // per-(n,c) extremes of x
__device__ float g_meanf[Nn], g_istdf[Nn];
__device__ float g_qscale;   // 128 / gamma
__device__ float g_coef;     // 0.01 * gamma / 128
__device__ float g_delta;    // 0.7 * mean|w|

// ---------------------------------------------------------------------------
// Portable PTX helpers (sm_80+ only; must compile under plain sm_100)
// ---------------------------------------------------------------------------
__device__ __forceinline__ uint32_t smem_u32(const void* p) {
    uint32_t a;
    asm("{ .reg .u64 t; cvta.to.shared.u64 t, %1; cvt.u32.u64 %0, t; }" : "=r"(a) : "l"(p));
    return a;
}
__device__ __forceinline__ void cp16(uint32_t dst, const void* src) {
    asm volatile("cp.async.cg.shared.global [%0], [%1], 16;" :: "r"(dst), "l"(src) : "memory");
}
__device__ __forceinline__ void cp_commit() {
    asm volatile("cp.async.commit_group;" ::: "memory");
}
__device__ __forceinline__ void ldsm_x4(uint32_t a, uint32_t& r0, uint32_t& r1,
                                        uint32_t& r2, uint32_t& r3) {
    asm volatile("ldmatrix.sync.aligned.m8n8.x4.shared.b16 {%0,%1,%2,%3}, [%4];"
                 : "=r"(r0), "=r"(r1), "=r"(r2), "=r"(r3) : "r"(a));
}
__device__ __forceinline__ void ldsm_x4t(uint32_t a, uint32_t& r0, uint32_t& r1,
                                         uint32_t& r2, uint32_t& r3) {
    asm volatile("ldmatrix.sync.aligned.m8n8.x4.trans.shared.b16 {%0,%1,%2,%3}, [%4];"
                 : "=r"(r0), "=r"(r1), "=r"(r2), "=r"(r3) : "r"(a));
}
__device__ __forceinline__ void mma16816(float* d, const uint32_t* a,
                                         uint32_t b0, uint32_t b1) {
    asm volatile(
        "mma.sync.aligned.m16n8k16.row.col.f32.bf16.bf16.f32 "
        "{%0,%1,%2,%3}, {%4,%5,%6,%7}, {%8,%9}, {%0,%1,%2,%3};"
        : "+f"(d[0]), "+f"(d[1]), "+f"(d[2]), "+f"(d[3])
        : "r"(a[0]), "r"(a[1]), "r"(a[2]), "r"(a[3]), "r"(b0), "r"(b1));
}

// ---------------------------------------------------------------------------
// K0: zero reduction scratch
// ---------------------------------------------------------------------------
__global__ void k_init() {
    int t = threadIdx.x;
    if (t < Nn) { g_sum[t] = 0.0; g_sumsq[t] = 0.0; }
    if (t == 0) { g_wabs = 0.0; }
}

// ---------------------------------------------------------------------------
// K1: per-sample sum / sumsq + exact per-(n,c) min/max of x.
// Each block covers exactly 4 whole channels (16384 contiguous elems).
// ---------------------------------------------------------------------------
__global__ void k_stats(const float* __restrict__ x) {
    int n = blockIdx.y;
    const float* p = x + (size_t)n * NPIX + (size_t)blockIdx.x * 16384;
    int tid = threadIdx.x;
    float s = 0.f, ss = 0.f;
    float mn[4] = {3.4e38f, 3.4e38f, 3.4e38f, 3.4e38f};
    float mx[4] = {-3.4e38f, -3.4e38f, -3.4e38f, -3.4e38f};
#pragma unroll
    for (int k = 0; k < 16; k++) {
        int ch = k >> 2;                       // constant per unrolled iter
        float4 v = *(const float4*)(p + tid * 4 + k * 1024);
        s  += v.x + v.y + v.z + v.w;
        ss += v.x*v.x + v.y*v.y + v.z*v.z + v.w*v.w;
        mn[ch] = fminf(mn[ch], fminf(fminf(v.x, v.y), fminf(v.z, v.w)));
        mx[ch] = fmaxf(mx[ch], fmaxf(fmaxf(v.x, v.y), fmaxf(v.z, v.w)));
    }
#pragma unroll
    for (int off = 16; off; off >>= 1) {
        s  += __shfl_xor_sync(0xffffffffu, s,  off);
        ss += __shfl_xor_sync(0xffffffffu, ss, off);
#pragma unroll
        for (int j = 0; j < 4; j++) {
            mn[j] = fminf(mn[j], __shfl_xor_sync(0xffffffffu, mn[j], off));
            mx[j] = fmaxf(mx[j], __shfl_xor_sync(0xffffffffu, mx[j], off));
        }
    }
    __shared__ double ws[8], wss[8];
    __shared__ float smn[8][4], smx[8][4];
    int wid = tid >> 5, lane = tid & 31;
    if (lane == 0) {
        ws[wid] = (double)s; wss[wid] = (double)ss;
#pragma unroll
        for (int j = 0; j < 4; j++) { smn[wid][j] = mn[j]; smx[wid][j] = mx[j]; }
    }
    __syncthreads();
    if (tid == 0) {
        double S = 0.0, SS = 0.0;
#pragma unroll
        for (int i = 0; i < 8; i++) { S += ws[i]; SS += wss[i]; }
        atomicAdd(&g_sum[n], S);
        atomicAdd(&g_sumsq[n], SS);
    }
    if (tid < 4) {
        float a = 3.4e38f, bmax = -3.4e38f;
#pragma unroll
        for (int w = 0; w < 8; w++) {
            a = fminf(a, smn[w][tid]);
            bmax = fmaxf(bmax, smx[w][tid]);
        }
        int c = blockIdx.x * 4 + tid;
        g_cmin[n * Cc + c] = a;
        g_cmax[n * Cc + c] = bmax;
    }
}

// ---------------------------------------------------------------------------
// K1w: sum |w|
// ---------------------------------------------------------------------------
__global__ void k_wabs(const float* __restrict__ w) {
    int tid = threadIdx.x;
    float s = 0.f;
    for (int i = blockIdx.x * 256 + tid; i < WTOT; i += gridDim.x * 256)
        s += fabsf(w[i]);
#pragma unroll
    for (int off = 16; off; off >>= 1) s += __shfl_xor_sync(0xffffffffu, s, off);
    __shared__ double ws[8];
    int wid = tid >> 5, lane = tid & 31;
    if (lane == 0) ws[wid] = (double)s;
    __syncthreads();
    if (tid == 0) {
        double S = 0.0;
#pragma unroll
        for (int i = 0; i < 8; i++) S += ws[i];
        atomicAdd(&g_wabs, S);
    }
}

__device__ __forceinline__ void sample_stats(int n, float& fm, float& istd) {
    double S = g_sum[n], SS = g_sumsq[n];
    double m = S * (1.0 / (double)NPIX);
    double v = SS * (1.0 / (double)NPIX) - m * m;
    fm = (float)m;
    istd = 1.0f / sqrtf((float)v + GN_EPSF);
}

// ---------------------------------------------------------------------------
// K2: finalize scalars.  gamma from per-channel endpoints (affine GroupNorm
// is monotone in x per (n,c), so |.| max is at an endpoint; identical fp
// formula applied to actual data values -> bit-identical to elementwise max).
// ---------------------------------------------------------------------------
__global__ void k_post(const float* __restrict__ lnw, const float* __restrict__ lnb) {
    __shared__ float sm[Nn], si[Nn];
    __shared__ float wred[8];
    int tid = threadIdx.x;
    if (tid < Nn) {
        float fm, istd;
        sample_stats(tid, fm, istd);
        g_meanf[tid] = fm; g_istdf[tid] = istd;
        sm[tid] = fm; si[tid] = istd;
    }
    __syncthreads();
    float m = 0.f;
#pragma unroll
    for (int it = 0; it < 16; it++) {
        int idx = it * 256 + tid;
        int n = idx >> 8, c = idx & 255;
        float fm = sm[n], istd = si[n], g = lnw[c], bb = lnb[c];
        m = fmaxf(m, fabsf(((g_cmin[idx] - fm) * istd) * g + bb));
        m = fmaxf(m, fabsf(((g_cmax[idx] - fm) * istd) * g + bb));
    }
#pragma unroll
    for (int off = 16; off; off >>= 1) m = fmaxf(m, __shfl_xor_sync(0xffffffffu, m, off));
    int wid = tid >> 5, lane = tid & 31;
    if (lane == 0) wred[wid] = m;
    __syncthreads();
    if (tid == 0) {
#pragma unroll
        for (int i = 1; i < 8; i++) m = fmaxf(m, wred[i]);
        float gamma = fmaxf(m, 1e-6f);
        g_qscale = 128.0f / gamma;
        g_coef = 0.01f * gamma * (1.0f / 128.0f);
        g_delta = 0.7f * (float)(g_wabs * (1.0 / (double)WTOT));
    }
}

// ---------------------------------------------------------------------------
// K3a: zero the halo of g_xq
// ---------------------------------------------------------------------------
__global__ void k_halo() {
    int idx = blockIdx.x * 256 + threadIdx.x;       // 520 blocks
    int n = idx / (260 * 32);
    int r = idx - n * (260 * 32);
    int p = r >> 5, q = r & 31;
    int ph, pw;
    if (p < 66)       { ph = 0;       pw = p; }
    else if (p < 132) { ph = 65;      pw = p - 66; }
    else if (p < 196) { ph = p - 131; pw = 0; }
    else              { ph = p - 195; pw = 65; }
    uint4 z = make_uint4(0, 0, 0, 0);
    *(uint4*)(g_xq + ((size_t)(n * PP + ph) * PP + pw) * Cc + q * 8) = z;
}

// ---------------------------------------------------------------------------
// K3: quantize + NCHW->NHWC transpose into padded bf16 scratch
// ---------------------------------------------------------------------------
__global__ void k_quant_t(const float* __restrict__ x,
                          const float* __restrict__ lnw,
                          const float* __restrict__ lnb) {
    __shared__ float sm[64][68];
    int b = blockIdx.x;
    int ic4 = b & 3, h = (b >> 2) & 63, n = b >> 8;
    int tid = threadIdx.x;
    float mean = g_meanf[n], istd = g_istdf[n], qs = g_qscale;

    const float* xb = x + ((size_t)n * Cc + ic4 * 64) * 4096 + h * 64;
#pragma unroll
    for (int i = tid; i < 1024; i += 256) {
        int row = i >> 4, c4 = i & 15;
        float4 v = *(const float4*)(xb + (size_t)row * 4096 + c4 * 4);
        *(float4*)&sm[row][c4 * 4] = v;
    }
    __syncthreads();

    __nv_bfloat16* ob = g_xq + ((size_t)(n * PP + h + 1) * PP + 1) * Cc + ic4 * 64;
#pragma unroll
    for (int j = tid; j < 512; j += 256) {
        int p = j >> 3, seg = j & 7;
        unsigned short hv[8];
#pragma unroll
        for (int e = 0; e < 8; e++) {
            int cl = seg * 8 + e;
            int c = ic4 * 64 + cl;
            float v = sm[cl][p];
            float xl = ((v - mean) * istd) * lnw[c] + lnb[c];
            float z = fminf(fmaxf(xl * qs, -128.0f), 128.0f);
            hv[e] = __bfloat16_as_ushort(__float2bfloat16_rn(rintf(z)));
        }
        uint4 u;
        u.x = (uint32_t)hv[0] | ((uint32_t)hv[1] << 16);
        u.y = (uint32_t)hv[2] | ((uint32_t)hv[3] << 16);
        u.z = (uint32_t)hv[4] | ((uint32_t)hv[5] << 16);
        u.w = (uint32_t)hv[6] | ((uint32_t)hv[7] << 16);
        *(uint4*)(ob + (size_t)p * Cc + seg * 8) = u;
    }
}

// ---------------------------------------------------------------------------
// K3w: ternarize weights -> bf16 [tap][ic][oc]
// ---------------------------------------------------------------------------
__global__ void k_wq(const float* __restrict__ w) {
    int idx = blockIdx.x * 256 + threadIdx.x;       // 2304 blocks
    int tap = idx >> 16;
    int rem = idx & 65535;
    int ic = rem >> 8, oc = rem & 255;
    float v = w[(size_t)(oc * Cc + ic) * 9 + tap];
    float d = g_delta;
    float q = (v > d) ? 1.f : ((v < -d) ? -1.f : 0.f);
    g_wq[idx] = __float2bfloat16_rn(q);
}

// ---------------------------------------------------------------------------
// K4: implicit-GEMM conv via mma.sync with kx tap-reuse A strips.
// CTA: 128 px (2 rows x 64 cols) x 128 oc.  24 chunks = ky(3) x ic-chunk(8).
// Per chunk: one 2x66-px A strip (covers kx=0..2) + 3 B tap-tiles.
// 3-stage cp.async ring; 8 warps 2(M) x 4(N); warp 64px x 32oc; 64 accums.
// ---------------------------------------------------------------------------
#define STAGES 3
#define A_BYTES 8448                  // 132 strip-px * 64 B
#define STAGE_B (A_BYTES + 3 * 8192)  // 33024
#define CONV_SMEM (STAGES * STAGE_B)  // 99072; epilogue reuse needs 64KB

__global__ void __launch_bounds__(256, 2)
k_conv(const float* __restrict__ bias, float* __restrict__ out) {
    extern __shared__ __align__(1024) char smem[];
    uint32_t sb = smem_u32(smem);
    float* sbuf = (float*)smem;

    int tid = threadIdx.x, lid = tid & 31, wid = tid >> 5;
    int wm = wid & 1, wn = wid >> 1;              // warp grid 2(M) x 4(N)
    int b = blockIdx.x;
    int ocb = b & 1, rp = (b >> 1) & 31, n = b >> 6;
    int y0 = rp * 2, ocBase = ocb * 128;

    const __nv_bfloat16* xqn = g_xq + (size_t)n * PP * PP * Cc;

    int bk0 = tid >> 4, bc0 = tid & 15;           // B staging coords
    uint32_t bsw = (uint32_t)(bc0 ^ (bk0 & 7)) << 4;

    float d[4][4][4];
#pragma unroll
    for (int i = 0; i < 4; i++)
#pragma unroll
        for (int j = 0; j < 4; j++)
#pragma unroll
            for (int e = 0; e < 4; e++) d[i][j][e] = 0.f;

    auto stage = [&](int ch, int s) {
        if (ch < 24) {
            int ky = ch >> 3, icc = ch & 7;
            int ic0 = icc * 32;
            uint32_t As = sb + s * STAGE_B;
            uint32_t Bs = As + A_BYTES;
            // A strip: 132 px (2 rows x 66 cols) x 32 ic = 528 cp16
#pragma unroll
            for (int rr = 0; rr < 3; rr++) {
                int idx = tid + rr * 256;
                if (rr < 2 || tid < 16) {
                    int px = idx >> 2, c = idx & 3;
                    int row = (px >= 66) ? 1 : 0;
                    int col = px - row * 66;
                    cp16(As + px * 64 + ((c ^ ((px >> 1) & 3)) << 4),
                         xqn + ((size_t)(y0 + ky + row) * PP + col) * Cc + ic0 + c * 8);
                }
            }
            // B: 3 kx taps, each 32 ic x 128 oc (R4-proven layout per tap)
#pragma unroll
            for (int t = 0; t < 3; t++) {
                const __nv_bfloat16* wb =
                    g_wq + (size_t)(ky * 3 + t) * 65536 + (size_t)ic0 * 256 + ocBase + bc0 * 8;
                uint32_t Bt = Bs + t * 8192;
                cp16(Bt + bk0 * 256 + bsw, wb + (size_t)bk0 * 256);
                cp16(Bt + (bk0 + 16) * 256 + bsw, wb + (size_t)(bk0 + 16) * 256);
            }
        }
        cp_commit();
    };

    stage(0, 0); stage(1, 1);

    int sc = 0, sp = 2;                            // consume slot, produce slot
    for (int it = 0; it < 24; it++) {
        __syncthreads();
        stage(it + 2, sp);
        asm volatile("cp.async.wait_group 2;" ::: "memory");
        __syncthreads();

        uint32_t As = sb + sc * STAGE_B;
        uint32_t Bs = As + A_BYTES;
#pragma unroll
        for (int kx = 0; kx < 3; kx++) {
            uint32_t Bt = Bs + kx * 8192;
#pragma unroll
            for (int g = 0; g < 2; g++) {
                uint32_t a[4][4];
#pragma unroll
                for (int i = 0; i < 4; i++) {
                    int px = wm * 64 + i * 16 + (lid & 15);
                    int pxs = (px >> 6) * 66 + (px & 63) + kx;
                    int kb = g * 2 + (lid >> 4);
                    int ph = kb ^ ((pxs >> 1) & 3);
                    ldsm_x4(As + pxs * 64 + ph * 16, a[i][0], a[i][1], a[i][2], a[i][3]);
                }
#pragma unroll
                for (int jj = 0; jj < 2; jj++) {
                    uint32_t bf[4];
                    int k = g * 16 + (lid & 15);
                    int cb = wn * 4 + jj * 2 + (lid >> 4);
                    int ph = cb ^ (k & 7);
                    ldsm_x4t(Bt + k * 256 + ph * 16, bf[0], bf[1], bf[2], bf[3]);
#pragma unroll
                    for (int i = 0; i < 4; i++) {
                        mma16816(d[i][jj * 2], a[i], bf[0], bf[1]);
                        mma16816(d[i][jj * 2 + 1], a[i], bf[2], bf[3]);
                    }
                }
            }
        }
        if (++sc == 3) sc = 0;
        if (++sp == 3) sp = 0;
    }
    asm volatile("cp.async.wait_group 0;" ::: "memory");
    __syncthreads();

    // ---- epilogue: per-warp smem transpose -> coalesced NCHW float4 stores ----
    int wb = wid * 2048;                           // 8KB float region per warp
    int q = lid >> 2, t2 = (lid & 3) * 2;
#pragma unroll
    for (int i = 0; i < 4; i++) {
#pragma unroll
        for (int j = 0; j < 4; j++) {
            int px = i * 16 + q;
            int oc = j * 8 + t2;
            sbuf[wb + oc * 64 + px]           = d[i][j][0];
            sbuf[wb + (oc + 1) * 64 + px]     = d[i][j][1];
            sbuf[wb + oc * 64 + px + 8]       = d[i][j][2];
            sbuf[wb + (oc + 1) * 64 + px + 8] = d[i][j][3];
        }
    }
    __syncwarp();
    float coef = g_coef;
    int y = y0 + wm;
#pragma unroll
    for (int itr = 0; itr < 16; itr++) {
        int ocl = itr * 2 + (lid >> 4);
        int x4 = (lid & 15) * 4;
        float4 v = *(float4*)&sbuf[wb + ocl * 64 + x4];
        int oc = ocBase + wn * 32 + ocl;
        float bz = bias[oc];
        v.x = v.x * coef + bz;
        v.y = v.y * coef + bz;
        v.z = v.z * coef + bz;
        v.w = v.w * coef + bz;
        *(float4*)(out + (((size_t)n * Cc + oc) * Hh + y) * Ww + x4) = v;
    }
}

// ---------------------------------------------------------------------------
// Host launch
// ---------------------------------------------------------------------------
extern "C" void kernel_launch(void* const* d_in, const int* in_sizes, int n_in,
                              void* d_out, int out_size) {
    const float* x    = (const float*)d_in[0];
    const float* w    = (const float*)d_in[1];
    const float* bias = (const float*)d_in[2];
    const float* lnw  = (const float*)d_in[3];
    const float* lnb  = (const float*)d_in[4];
    float* out = (float*)d_out;

    cudaFuncSetAttribute(k_conv, cudaFuncAttributeMaxDynamicSharedMemorySize, CONV_SMEM);

    k_init<<<1, 32>>>();
    k_stats<<<dim3(64, Nn), 256>>>(x);
    k_wabs<<<64, 256>>>(w);
    k_post<<<1, 256>>>(lnw, lnb);
    k_halo<<<520, 256>>>();
    k_quant_t<<<4096, 256>>>(x, lnw, lnb);
    k_wq<<<2304, 256>>>(w);
    k_conv<<<1024, 256, CONV_SMEM>>>(bias, out);
}

// round 10
// speedup vs baseline: 1.3301x; 1.3207x over previous
#include <cuda_runtime.h>
#include <cuda_bf16.h>
#include <math.h>
#include <stdint.h>

// ---------------------------------------------------------------------------
// Problem constants
// ---------------------------------------------------------------------------
#define Nn   16
#define Cc   256
#define Hh   64
#define Ww   64
#define PP   66                       // padded spatial (1 halo each side)
#define NPIX (Cc*Hh*Ww)               // per-sample elements (GroupNorm group)
#define XQTOT (Nn*PP*PP*Cc)           // NHWC padded int8 activations
#define WTOT (Cc*Cc*9)
#define GN_EPSF 1e-5f

// ---------------------------------------------------------------------------
// Scratch (__device__ globals; no allocation anywhere)
// ---------------------------------------------------------------------------
__device__ __align__(1024) signed char g_xq[XQTOT];   // [n][ph][pw][ic] int8
__device__ __align__(1024) signed char g_wq[WTOT];    // [tap][oc][ic], {-1,0,1}
__device__ double g_sum[Nn];
__device__ double g_sumsq[Nn];
__device__ double g_wabs;
__device__ float g_cmin[Nn*Cc], g_cmax[Nn*Cc];        // per-(n,c) extremes of x
__device__ float g_meanf[Nn], g_istdf[Nn];
__device__ float g_qscale;   // 128 / gamma
__device__ float g_coef;     // 0.01 * gamma / 128
__device__ float g_delta;    // 0.7 * mean|w|

// ---------------------------------------------------------------------------
// Portable PTX helpers (sm_80+ only; must compile under plain sm_100)
// ---------------------------------------------------------------------------
__device__ __forceinline__ uint32_t smem_u32(const void* p) {
    uint32_t a;
    asm("{ .reg .u64 t; cvta.to.shared.u64 t, %1; cvt.u32.u64 %0, t; }" : "=r"(a) : "l"(p));
    return a;
}
__device__ __forceinline__ void cp16(uint32_t dst, const void* src) {
    asm volatile("cp.async.cg.shared.global [%0], [%1], 16;" :: "r"(dst), "l"(src) : "memory");
}
__device__ __forceinline__ void cp_commit() {
    asm volatile("cp.async.commit_group;" ::: "memory");
}
__device__ __forceinline__ void ldsm_x4(uint32_t a, uint32_t& r0, uint32_t& r1,
                                        uint32_t& r2, uint32_t& r3) {
    asm volatile("ldmatrix.sync.aligned.m8n8.x4.shared.b16 {%0,%1,%2,%3}, [%4];"
                 : "=r"(r0), "=r"(r1), "=r"(r2), "=r"(r3) : "r"(a));
}
// int8 MMA: D(s32) = A(s8,row) * B(s8,col) + C(s32), 16x8x32
__device__ __forceinline__ void mma16832(int* d, const uint32_t* a,
                                         uint32_t b0, uint32_t b1) {
    asm volatile(
        "mma.sync.aligned.m16n8k32.row.col.s32.s8.s8.s32 "
        "{%0,%1,%2,%3}, {%4,%5,%6,%7}, {%8,%9}, {%0,%1,%2,%3};"
        : "+r"(d[0]), "+r"(d[1]), "+r"(d[2]), "+r"(d[3])
        : "r"(a[0]), "r"(a[1]), "r"(a[2]), "r"(a[3]), "r"(b0), "r"(b1));
}

// ---------------------------------------------------------------------------
// K0: zero reduction scratch
// ---------------------------------------------------------------------------
__global__ void k_init() {
    int t = threadIdx.x;
    if (t < Nn) { g_sum[t] = 0.0; g_sumsq[t] = 0.0; }
    if (t == 0) { g_wabs = 0.0; }
}

// ---------------------------------------------------------------------------
// K1: per-sample sum / sumsq + exact per-(n,c) min/max of x.
// Each block covers exactly 4 whole channels (16384 contiguous elems).
// ---------------------------------------------------------------------------
__global__ void k_stats(const float* __restrict__ x) {
    int n = blockIdx.y;
    const float* p = x + (size_t)n * NPIX + (size_t)blockIdx.x * 16384;
    int tid = threadIdx.x;
    float s = 0.f, ss = 0.f;
    float mn[4] = {3.4e38f, 3.4e38f, 3.4e38f, 3.4e38f};
    float mx[4] = {-3.4e38f, -3.4e38f, -3.4e38f, -3.4e38f};
#pragma unroll
    for (int k = 0; k < 16; k++) {
        int ch = k >> 2;
        float4 v = *(const float4*)(p + tid * 4 + k * 1024);
        s  += v.x + v.y + v.z + v.w;
        ss += v.x*v.x + v.y*v.y + v.z*v.z + v.w*v.w;
        mn[ch] = fminf(mn[ch], fminf(fminf(v.x, v.y), fminf(v.z, v.w)));
        mx[ch] = fmaxf(mx[ch], fmaxf(fmaxf(v.x, v.y), fmaxf(v.z, v.w)));
    }
#pragma unroll
    for (int off = 16; off; off >>= 1) {
        s  += __shfl_xor_sync(0xffffffffu, s,  off);
        ss += __shfl_xor_sync(0xffffffffu, ss, off);
#pragma unroll
        for (int j = 0; j < 4; j++) {
            mn[j] = fminf(mn[j], __shfl_xor_sync(0xffffffffu, mn[j], off));
            mx[j] = fmaxf(mx[j], __shfl_xor_sync(0xffffffffu, mx[j], off));
        }
    }
    __shared__ double ws[8], wss[8];
    __shared__ float smn[8][4], smx[8][4];
    int wid = tid >> 5, lane = tid & 31;
    if (lane == 0) {
        ws[wid] = (double)s; wss[wid] = (double)ss;
#pragma unroll
        for (int j = 0; j < 4; j++) { smn[wid][j] = mn[j]; smx[wid][j] = mx[j]; }
    }
    __syncthreads();
    if (tid == 0) {
        double S = 0.0, SS = 0.0;
#pragma unroll
        for (int i = 0; i < 8; i++) { S += ws[i]; SS += wss[i]; }
        atomicAdd(&g_sum[n], S);
        atomicAdd(&g_sumsq[n], SS);
    }
    if (tid < 4) {
        float a = 3.4e38f, bmax = -3.4e38f;
#pragma unroll
        for (int w = 0; w < 8; w++) {
            a = fminf(a, smn[w][tid]);
            bmax = fmaxf(bmax, smx[w][tid]);
        }
        int c = blockIdx.x * 4 + tid;
        g_cmin[n * Cc + c] = a;
        g_cmax[n * Cc + c] = bmax;
    }
}

// ---------------------------------------------------------------------------
// K1w: sum |w|
// ---------------------------------------------------------------------------
__global__ void k_wabs(const float* __restrict__ w) {
    int tid = threadIdx.x;
    float s = 0.f;
    for (int i = blockIdx.x * 256 + tid; i < WTOT; i += gridDim.x * 256)
        s += fabsf(w[i]);
#pragma unroll
    for (int off = 16; off; off >>= 1) s += __shfl_xor_sync(0xffffffffu, s, off);
    __shared__ double ws[8];
    int wid = tid >> 5, lane = tid & 31;
    if (lane == 0) ws[wid] = (double)s;
    __syncthreads();
    if (tid == 0) {
        double S = 0.0;
#pragma unroll
        for (int i = 0; i < 8; i++) S += ws[i];
        atomicAdd(&g_wabs, S);
    }
}

__device__ __forceinline__ void sample_stats(int n, float& fm, float& istd) {
    double S = g_sum[n], SS = g_sumsq[n];
    double m = S * (1.0 / (double)NPIX);
    double v = SS * (1.0 / (double)NPIX) - m * m;
    fm = (float)m;
    istd = 1.0f / sqrtf((float)v + GN_EPSF);
}

// ---------------------------------------------------------------------------
// K2: finalize scalars (gamma from per-channel endpoints; bit-identical)
// ---------------------------------------------------------------------------
__global__ void k_post(const float* __restrict__ lnw, const float* __restrict__ lnb) {
    __shared__ float sm[Nn], si[Nn];
    __shared__ float wred[8];
    int tid = threadIdx.x;
    if (tid < Nn) {
        float fm, istd;
        sample_stats(tid, fm, istd);
        g_meanf[tid] = fm; g_istdf[tid] = istd;
        sm[tid] = fm; si[tid] = istd;
    }
    __syncthreads();
    float m = 0.f;
#pragma unroll
    for (int it = 0; it < 16; it++) {
        int idx = it * 256 + tid;
        int n = idx >> 8, c = idx & 255;
        float fm = sm[n], istd = si[n], g = lnw[c], bb = lnb[c];
        m = fmaxf(m, fabsf(((g_cmin[idx] - fm) * istd) * g + bb));
        m = fmaxf(m, fabsf(((g_cmax[idx] - fm) * istd) * g + bb));
    }
#pragma unroll
    for (int off = 16; off; off >>= 1) m = fmaxf(m, __shfl_xor_sync(0xffffffffu, m, off));
    int wid = tid >> 5, lane = tid & 31;
    if (lane == 0) wred[wid] = m;
    __syncthreads();
    if (tid == 0) {
#pragma unroll
        for (int i = 1; i < 8; i++) m = fmaxf(m, wred[i]);
        float gamma = fmaxf(m, 1e-6f);
        g_qscale = 128.0f / gamma;
        g_coef = 0.01f * gamma * (1.0f / 128.0f);
        g_delta = 0.7f * (float)(g_wabs * (1.0 / (double)WTOT));
    }
}

// ---------------------------------------------------------------------------
// K3a: zero the halo of g_xq (260 border px/sample, 256 B each)
// ---------------------------------------------------------------------------
__global__ void k_halo() {
    int idx = blockIdx.x * 256 + threadIdx.x;       // 260 blocks
    int n = idx / (260 * 16);
    int r = idx - n * (260 * 16);
    int p = r >> 4, q = r & 15;
    int ph, pw;
    if (p < 66)       { ph = 0;       pw = p; }
    else if (p < 132) { ph = 65;      pw = p - 66; }
    else if (p < 196) { ph = p - 131; pw = 0; }
    else              { ph = p - 195; pw = 65; }
    uint4 z = make_uint4(0, 0, 0, 0);
    *(uint4*)(g_xq + ((size_t)(n * PP + ph) * PP + pw) * Cc + q * 16) = z;
}

// ---------------------------------------------------------------------------
// K3: quantize + NCHW->NHWC transpose into padded int8 scratch
// ---------------------------------------------------------------------------
__global__ void k_quant_t(const float* __restrict__ x,
                          const float* __restrict__ lnw,
                          const float* __restrict__ lnb) {
    __shared__ float sm[64][68];
    int b = blockIdx.x;
    int ic4 = b & 3, h = (b >> 2) & 63, n = b >> 8;
    int tid = threadIdx.x;
    float mean = g_meanf[n], istd = g_istdf[n], qs = g_qscale;

    const float* xb = x + ((size_t)n * Cc + ic4 * 64) * 4096 + h * 64;
#pragma unroll
    for (int i = tid; i < 1024; i += 256) {
        int row = i >> 4, c4 = i & 15;
        float4 v = *(const float4*)(xb + (size_t)row * 4096 + c4 * 4);
        *(float4*)&sm[row][c4 * 4] = v;
    }
    __syncthreads();

    signed char* ob = g_xq + ((size_t)(n * PP + h + 1) * PP + 1) * Cc + ic4 * 64;
#pragma unroll
    for (int j = tid; j < 512; j += 256) {
        int p = j >> 3, seg = j & 7;
        uint32_t lo = 0, hi = 0;
#pragma unroll
        for (int e = 0; e < 8; e++) {
            int cl = seg * 8 + e;
            int c = ic4 * 64 + cl;
            float v = sm[cl][p];
            float xl = ((v - mean) * istd) * lnw[c] + lnb[c];
            float z = fminf(fmaxf(xl * qs, -128.0f), 128.0f);
            int qi = (int)rintf(z);
            if (qi > 127) qi = 127;                 // int8 clamp (+128 -> 127)
            uint32_t bb = (uint32_t)(qi & 255);
            if (e < 4) lo |= bb << (8 * e);
            else       hi |= bb << (8 * (e - 4));
        }
        uint2 u = make_uint2(lo, hi);
        *(uint2*)(ob + (size_t)p * Cc + seg * 8) = u;
    }
}

// ---------------------------------------------------------------------------
// K3w: ternarize weights -> int8 [tap][oc][ic]  (B as NxK row-major)
// ---------------------------------------------------------------------------
__global__ void k_wq(const float* __restrict__ w) {
    int idx = blockIdx.x * 256 + threadIdx.x;       // 2304 blocks
    int tap = idx >> 16;
    int rem = idx & 65535;
    int oc = rem >> 8, ic = rem & 255;
    float v = w[(size_t)(oc * Cc + ic) * 9 + tap];
    float d = g_delta;
    g_wq[idx] = (v > d) ? 1 : ((v < -d) ? -1 : 0);
}

// ---------------------------------------------------------------------------
// K4: int8 implicit-GEMM conv via mma.sync.m16n8k32.s8 (exact integer math).
// CTA: 128 px (2 rows x 64 cols) x 128 oc.  24 chunks = ky(3) x ic-chunk(8).
// Per chunk: one 2x66-px A strip (serves kx=0..2) + 3 B tap-tiles (128oc x 32ic).
// 5-stage cp.async ring; 8 warps 2(M) x 4(N); warp 64px x 32oc; 64 s32 accums.
// Swizzle: 32B rows, 16B segs, phys_seg = seg ^ ((row>>2)&1)  (phase-exact).
// ---------------------------------------------------------------------------
#define STAGES 5
#define A_BYTES 4352                  // 132 px * 32 B (+pad)
#define STAGE_B (A_BYTES + 3 * 4096)  // 16640
#define CONV_SMEM (STAGES * STAGE_B)  // 83200; epilogue reuse needs 64KB

__global__ void __launch_bounds__(256, 2)
k_conv(const float* __restrict__ bias, float* __restrict__ out) {
    extern __shared__ __align__(1024) char smem[];
    uint32_t sb = smem_u32(smem);
    float* sbuf = (float*)smem;

    int tid = threadIdx.x, lid = tid & 31, wid = tid >> 5;
    int wm = wid & 1, wn = wid >> 1;              // warp grid 2(M) x 4(N)
    int b = blockIdx.x;
    int ocb = b & 1, rp = (b >> 1) & 31, n = b >> 6;
    int y0 = rp * 2, ocBase = ocb * 128;

    const signed char* xqn = g_xq + (size_t)n * PP * PP * Cc;

    int d[4][4][4];
#pragma unroll
    for (int i = 0; i < 4; i++)
#pragma unroll
        for (int j = 0; j < 4; j++)
#pragma unroll
            for (int e = 0; e < 4; e++) d[i][j][e] = 0;

    // staging coords
    int apx = tid >> 1, aseg = tid & 1;           // A: px 0..127 (+128..131 extra)
    int boc = tid >> 1, bseg = tid & 1;           // B: oc 0..127, seg 0..1

    auto stage = [&](int ch, int s) {
        if (ch < 24) {
            int ky = ch >> 3, icc = ch & 7;
            int ic0 = icc * 32;
            uint32_t As = sb + s * STAGE_B;
            uint32_t Bs = As + A_BYTES;
            // A strip: 132 px x 32 int8 = 264 cp16
            {
                int row = (apx >= 66) ? 1 : 0;
                int col = apx - row * 66;
                cp16(As + apx * 32 + ((aseg ^ ((apx >> 2) & 1)) << 4),
                     xqn + ((size_t)(y0 + ky + row) * PP + col) * Cc + ic0 + aseg * 16);
                if (tid < 8) {
                    int px2 = 128 + (tid >> 1);
                    int sg2 = tid & 1;
                    int col2 = px2 - 66;          // px2 in 128..131 -> row 1
                    cp16(As + px2 * 32 + ((sg2 ^ ((px2 >> 2) & 1)) << 4),
                         xqn + ((size_t)(y0 + ky + 1) * PP + col2) * Cc + ic0 + sg2 * 16);
                }
            }
            // B: 3 kx taps, each 128 oc x 32 ic = 256 cp16
#pragma unroll
            for (int t = 0; t < 3; t++) {
                cp16(Bs + t * 4096 + boc * 32 + ((bseg ^ ((boc >> 2) & 1)) << 4),
                     g_wq + (size_t)(ky * 3 + t) * 65536 + (size_t)(ocBase + boc) * 256
                          + ic0 + bseg * 16);
            }
        }
        cp_commit();
    };

    stage(0, 0); stage(1, 1); stage(2, 2); stage(3, 3);

    int sc = 0, sp = 4;                            // consume slot, produce slot
    for (int it = 0; it < 24; it++) {
        __syncthreads();
        stage(it + 4, sp);
        asm volatile("cp.async.wait_group 4;" ::: "memory");
        __syncthreads();

        uint32_t As = sb + sc * STAGE_B;
        uint32_t Bs = As + A_BYTES;
        int grp = lid >> 3, rr = lid & 7;
#pragma unroll
        for (int kx = 0; kx < 3; kx++) {
            uint32_t Bt = Bs + kx * 4096;
            uint32_t a[4][4];
#pragma unroll
            for (int i = 0; i < 4; i++) {
                int px = wm * 64 + i * 16 + ((grp & 1) << 3) + rr;
                int pxs = (px >> 6) * 66 + (px & 63) + kx;
                int seg = grp >> 1;
                ldsm_x4(As + pxs * 32 + ((seg ^ ((pxs >> 2) & 1)) << 4),
                        a[i][0], a[i][1], a[i][2], a[i][3]);
            }
#pragma unroll
            for (int m = 0; m < 2; m++) {
                uint32_t bf[4];
                int ocr = wn * 32 + m * 16 + ((grp >> 1) << 3) + rr;
                int seg = grp & 1;
                ldsm_x4(Bt + ocr * 32 + ((seg ^ ((ocr >> 2) & 1)) << 4),
                        bf[0], bf[1], bf[2], bf[3]);
#pragma unroll
                for (int i = 0; i < 4; i++) {
                    mma16832(d[i][m * 2], a[i], bf[0], bf[1]);
                    mma16832(d[i][m * 2 + 1], a[i], bf[2], bf[3]);
                }
            }
        }
        if (++sc == STAGES) sc = 0;
        if (++sp == STAGES) sp = 0;
    }
    asm volatile("cp.async.wait_group 0;" ::: "memory");
    __syncthreads();

    // ---- epilogue: per-warp smem transpose -> coalesced NCHW float4 stores ----
    int wb = wid * 2048;                           // 8KB float region per warp
    int q = lid >> 2, t2 = (lid & 3) * 2;
#pragma unroll
    for (int i = 0; i < 4; i++) {
#pragma unroll
        for (int j = 0; j < 4; j++) {
            int px = i * 16 + q;
            int oc = j * 8 + t2;
            sbuf[wb + oc * 64 + px]           = (float)d[i][j][0];
            sbuf[wb + (oc + 1) * 64 + px]     = (float)d[i][j][1];
            sbuf[wb + oc * 64 + px + 8]       = (float)d[i][j][2];
            sbuf[wb + (oc + 1) * 64 + px + 8] = (float)d[i][j][3];
        }
    }
    __syncwarp();
    float coef = g_coef;
    int y = y0 + wm;
#pragma unroll
    for (int itr = 0; itr < 16; itr++) {
        int ocl = itr * 2 + (lid >> 4);
        int x4 = (lid & 15) * 4;
        float4 v = *(float4*)&sbuf[wb + ocl * 64 + x4];
        int oc = ocBase + wn * 32 + ocl;
        float bz = bias[oc];
        v.x = v.x * coef + bz;
        v.y = v.y * coef + bz;
        v.z = v.z * coef + bz;
        v.w = v.w * coef + bz;
        *(float4*)(out + (((size_t)n * Cc + oc) * Hh + y) * Ww + x4) = v;
    }
}

// ---------------------------------------------------------------------------
// Host launch
// ---------------------------------------------------------------------------
extern "C" void kernel_launch(void* const* d_in, const int* in_sizes, int n_in,
                              void* d_out, int out_size) {
    const float* x    = (const float*)d_in[0];
    const float* w    = (const float*)d_in[1];
    const float* bias = (const float*)d_in[2];
    const float* lnw  = (const float*)d_in[3];
    const float* lnb  = (const float*)d_in[4];
    float* out = (float*)d_out;

    cudaFuncSetAttribute(k_conv, cudaFuncAttributeMaxDynamicSharedMemorySize, CONV_SMEM);

    k_init<<<1, 32>>>();
    k_stats<<<dim3(64, Nn), 256>>>(x);
    k_wabs<<<64, 256>>>(w);
    k_post<<<1, 256>>>(lnw, lnb);
    k_halo<<<260, 256>>>();
    k_quant_t<<<4096, 256>>>(x, lnw, lnb);
    k_wq<<<2304, 256>>>(w);
    k_conv<<<1024, 256, CONV_SMEM>>>(bias, out);
}

// round 11
// speedup vs baseline: 1.3473x; 1.0129x over previous
#include <cuda_runtime.h>
#include <cuda_bf16.h>
#include <math.h>
#include <stdint.h>

// ---------------------------------------------------------------------------
// Problem constants
// ---------------------------------------------------------------------------
#define Nn   16
#define Cc   256
#define Hh   64
#define Ww   64
#define PP   66                       // padded spatial (1 halo each side)
#define NPIX (Cc*Hh*Ww)               // per-sample elements (GroupNorm group)
#define XQTOT (Nn*PP*PP*Cc)           // NHWC padded int8 activations
#define WTOT (Cc*Cc*9)
#define GN_EPSF 1e-5f

// ---------------------------------------------------------------------------
// Scratch (__device__ globals; no allocation anywhere)
// ---------------------------------------------------------------------------
__device__ __align__(1024) signed char g_xq[XQTOT];   // [n][ph][pw][ic] int8
__device__ __align__(1024) signed char g_wq[WTOT];    // [tap][oc][ic], {-1,0,1}
__device__ double g_spart[Nn*64], g_sspart[Nn*64];    // per-block stat partials
__device__ double g_wpart[64];                        // |w| partials
__device__ float g_cmin[Nn*Cc], g_cmax[Nn*Cc];        // per-(n,c) extremes of x
__device__ float g_meanf[Nn], g_istdf[Nn];
__device__ float g_qscale;   // 128 / gamma
__device__ float g_coef;     // 0.01 * gamma / 128
__device__ float g_delta;    // 0.7 * mean|w|

// ---------------------------------------------------------------------------
// Portable PTX helpers (sm_80+ only; must compile under plain sm_100)
// ---------------------------------------------------------------------------
__device__ __forceinline__ uint32_t smem_u32(const void* p) {
    uint32_t a;
    asm("{ .reg .u64 t; cvta.to.shared.u64 t, %1; cvt.u32.u64 %0, t; }" : "=r"(a) : "l"(p));
    return a;
}
__device__ __forceinline__ void cp16(uint32_t dst, const void* src) {
    asm volatile("cp.async.cg.shared.global [%0], [%1], 16;" :: "r"(dst), "l"(src) : "memory");
}
__device__ __forceinline__ void cp_commit() {
    asm volatile("cp.async.commit_group;" ::: "memory");
}
__device__ __forceinline__ void ldsm_x4(uint32_t a, uint32_t& r0, uint32_t& r1,
                                        uint32_t& r2, uint32_t& r3) {
    asm volatile("ldmatrix.sync.aligned.m8n8.x4.shared.b16 {%0,%1,%2,%3}, [%4];"
                 : "=r"(r0), "=r"(r1), "=r"(r2), "=r"(r3) : "r"(a));
}
// int8 MMA: D(s32) = A(s8,row) * B(s8,col) + C(s32), 16x8x32
__device__ __forceinline__ void mma16832(int* d, const uint32_t* a,
                                         uint32_t b0, uint32_t b1) {
    asm volatile(
        "mma.sync.aligned.m16n8k32.row.col.s32.s8.s8.s32 "
        "{%0,%1,%2,%3}, {%4,%5,%6,%7}, {%8,%9}, {%0,%1,%2,%3};"
        : "+r"(d[0]), "+r"(d[1]), "+r"(d[2]), "+r"(d[3])
        : "r"(a[0]), "r"(a[1]), "r"(a[2]), "r"(a[3]), "r"(b0), "r"(b1));
}

// ---------------------------------------------------------------------------
// K1: per-sample sum/sumsq partials + exact per-(n,c) min/max of x.
// Each block covers exactly 4 whole channels (16384 contiguous elems).
// ---------------------------------------------------------------------------
__global__ void k_stats(const float* __restrict__ x) {
    int n = blockIdx.y;
    const float* p = x + (size_t)n * NPIX + (size_t)blockIdx.x * 16384;
    int tid = threadIdx.x;
    float s = 0.f, ss = 0.f;
    float mn[4] = {3.4e38f, 3.4e38f, 3.4e38f, 3.4e38f};
    float mx[4] = {-3.4e38f, -3.4e38f, -3.4e38f, -3.4e38f};
#pragma unroll
    for (int k = 0; k < 16; k++) {
        int ch = k >> 2;
        float4 v = *(const float4*)(p + tid * 4 + k * 1024);
        s  += v.x + v.y + v.z + v.w;
        ss += v.x*v.x + v.y*v.y + v.z*v.z + v.w*v.w;
        mn[ch] = fminf(mn[ch], fminf(fminf(v.x, v.y), fminf(v.z, v.w)));
        mx[ch] = fmaxf(mx[ch], fmaxf(fmaxf(v.x, v.y), fmaxf(v.z, v.w)));
    }
#pragma unroll
    for (int off = 16; off; off >>= 1) {
        s  += __shfl_xor_sync(0xffffffffu, s,  off);
        ss += __shfl_xor_sync(0xffffffffu, ss, off);
#pragma unroll
        for (int j = 0; j < 4; j++) {
            mn[j] = fminf(mn[j], __shfl_xor_sync(0xffffffffu, mn[j], off));
            mx[j] = fmaxf(mx[j], __shfl_xor_sync(0xffffffffu, mx[j], off));
        }
    }
    __shared__ double ws[8], wss[8];
    __shared__ float smn[8][4], smx[8][4];
    int wid = tid >> 5, lane = tid & 31;
    if (lane == 0) {
        ws[wid] = (double)s; wss[wid] = (double)ss;
#pragma unroll
        for (int j = 0; j < 4; j++) { smn[wid][j] = mn[j]; smx[wid][j] = mx[j]; }
    }
    __syncthreads();
    if (tid == 0) {
        double S = 0.0, SS = 0.0;
#pragma unroll
        for (int i = 0; i < 8; i++) { S += ws[i]; SS += wss[i]; }
        g_spart[n * 64 + blockIdx.x] = S;
        g_sspart[n * 64 + blockIdx.x] = SS;
    }
    if (tid < 4) {
        float a = 3.4e38f, bmax = -3.4e38f;
#pragma unroll
        for (int w = 0; w < 8; w++) {
            a = fminf(a, smn[w][tid]);
            bmax = fmaxf(bmax, smx[w][tid]);
        }
        int c = blockIdx.x * 4 + tid;
        g_cmin[n * Cc + c] = a;
        g_cmax[n * Cc + c] = bmax;
    }
}

// ---------------------------------------------------------------------------
// K1w: |w| partials
// ---------------------------------------------------------------------------
__global__ void k_wabs(const float* __restrict__ w) {
    int tid = threadIdx.x;
    float s = 0.f;
    for (int i = blockIdx.x * 256 + tid; i < WTOT; i += gridDim.x * 256)
        s += fabsf(w[i]);
#pragma unroll
    for (int off = 16; off; off >>= 1) s += __shfl_xor_sync(0xffffffffu, s, off);
    __shared__ double ws[8];
    int wid = tid >> 5, lane = tid & 31;
    if (lane == 0) ws[wid] = (double)s;
    __syncthreads();
    if (tid == 0) {
        double S = 0.0;
#pragma unroll
        for (int i = 0; i < 8; i++) S += ws[i];
        g_wpart[blockIdx.x] = S;
    }
}

// ---------------------------------------------------------------------------
// K2: reduce partials, finalize scalars (gamma from per-channel endpoints;
// same fp formula on actual data values -> bit-identical to elementwise max)
// ---------------------------------------------------------------------------
__global__ void k_post(const float* __restrict__ lnw, const float* __restrict__ lnb) {
    __shared__ float sm[Nn], si[Nn];
    __shared__ double swabs;
    __shared__ float wred[32];
    int tid = threadIdx.x;
    if (tid < Nn) {
        double S = 0.0, SS = 0.0;
#pragma unroll
        for (int i = 0; i < 64; i++) {
            S += g_spart[tid * 64 + i];
            SS += g_sspart[tid * 64 + i];
        }
        double mm = S * (1.0 / (double)NPIX);
        double vv = SS * (1.0 / (double)NPIX) - mm * mm;
        float fm = (float)mm;
        float istd = 1.0f / sqrtf((float)vv + GN_EPSF);
        g_meanf[tid] = fm; g_istdf[tid] = istd;
        sm[tid] = fm; si[tid] = istd;
    }
    if (tid == 16) {
        double W = 0.0;
#pragma unroll
        for (int i = 0; i < 64; i++) W += g_wpart[i];
        swabs = W;
    }
    __syncthreads();
    float m = 0.f;
#pragma unroll
    for (int it = 0; it < 4; it++) {
        int idx = it * 1024 + tid;
        int n = idx >> 8, c = idx & 255;
        float fm = sm[n], istd = si[n], g = lnw[c], bb = lnb[c];
        m = fmaxf(m, fabsf(((g_cmin[idx] - fm) * istd) * g + bb));
        m = fmaxf(m, fabsf(((g_cmax[idx] - fm) * istd) * g + bb));
    }
#pragma unroll
    for (int off = 16; off; off >>= 1) m = fmaxf(m, __shfl_xor_sync(0xffffffffu, m, off));
    int wid = tid >> 5, lane = tid & 31;
    if (lane == 0) wred[wid] = m;
    __syncthreads();
    if (tid == 0) {
#pragma unroll
        for (int i = 1; i < 32; i++) m = fmaxf(m, wred[i]);
        float gamma = fmaxf(m, 1e-6f);
        g_qscale = 128.0f / gamma;
        g_coef = 0.01f * gamma * (1.0f / 128.0f);
        g_delta = 0.7f * (float)(swabs * (1.0 / (double)WTOT));
    }
}

// ---------------------------------------------------------------------------
// K3: quantize + NCHW->NHWC transpose into padded int8 scratch
// ---------------------------------------------------------------------------
__global__ void k_quant_t(const float* __restrict__ x,
                          const float* __restrict__ lnw,
                          const float* __restrict__ lnb) {
    __shared__ float sm[64][68];
    int b = blockIdx.x;
    int ic4 = b & 3, h = (b >> 2) & 63, n = b >> 8;
    int tid = threadIdx.x;
    float mean = g_meanf[n], istd = g_istdf[n], qs = g_qscale;

    const float* xb = x + ((size_t)n * Cc + ic4 * 64) * 4096 + h * 64;
#pragma unroll
    for (int i = tid; i < 1024; i += 256) {
        int row = i >> 4, c4 = i & 15;
        float4 v = *(const float4*)(xb + (size_t)row * 4096 + c4 * 4);
        *(float4*)&sm[row][c4 * 4] = v;
    }
    __syncthreads();

    signed char* ob = g_xq + ((size_t)(n * PP + h + 1) * PP + 1) * Cc + ic4 * 64;
#pragma unroll
    for (int j = tid; j < 512; j += 256) {
        int p = j >> 3, seg = j & 7;
        uint32_t lo = 0, hi = 0;
#pragma unroll
        for (int e = 0; e < 8; e++) {
            int cl = seg * 8 + e;
            int c = ic4 * 64 + cl;
            float v = sm[cl][p];
            float xl = ((v - mean) * istd) * lnw[c] + lnb[c];
            float z = fminf(fmaxf(xl * qs, -128.0f), 128.0f);
            int qi = (int)rintf(z);
            if (qi > 127) qi = 127;                 // int8 clamp (+128 -> 127)
            uint32_t bb = (uint32_t)(qi & 255);
            if (e < 4) lo |= bb << (8 * e);
            else       hi |= bb << (8 * (e - 4));
        }
        uint2 u = make_uint2(lo, hi);
        *(uint2*)(ob + (size_t)p * Cc + seg * 8) = u;
    }
}

// ---------------------------------------------------------------------------
// K3w: ternarize weights -> int8 [tap][oc][ic]  +  halo zeroing (merged)
// blocks [0,2304): weights;  blocks [2304,2564): halo
// ---------------------------------------------------------------------------
__global__ void k_wq_halo(const float* __restrict__ w) {
    int bx = blockIdx.x;
    int tid = threadIdx.x;
    if (bx < 2304) {
        int idx = bx * 256 + tid;
        int tap = idx >> 16;
        int rem = idx & 65535;
        int oc = rem >> 8, ic = rem & 255;
        float v = w[(size_t)(oc * Cc + ic) * 9 + tap];
        float d = g_delta;
        g_wq[idx] = (v > d) ? 1 : ((v < -d) ? -1 : 0);
    } else {
        int idx = (bx - 2304) * 256 + tid;          // 260 blocks
        int n = idx / (260 * 16);
        int r = idx - n * (260 * 16);
        int p = r >> 4, q = r & 15;
        int ph, pw;
        if (p < 66)       { ph = 0;       pw = p; }
        else if (p < 132) { ph = 65;      pw = p - 66; }
        else if (p < 196) { ph = p - 131; pw = 0; }
        else              { ph = p - 195; pw = 65; }
        uint4 z = make_uint4(0, 0, 0, 0);
        *(uint4*)(g_xq + ((size_t)(n * PP + ph) * PP + pw) * Cc + q * 16) = z;
    }
}

// ---------------------------------------------------------------------------
// K4: int8 implicit-GEMM conv, CTA = 256 px (4 rows) x 128 oc, 512 threads.
// 12 chunks = ky(3) x 64-ic chunk(4).  Per chunk: 4-row x 66-col A strip
// (serves kx=0..2) + 3 B tap-tiles (128 oc x 64 ic).
// 4-stage cp.async ring; 16 warps 4(M) x 4(N); warp 64px x 32oc; 64 s32 acc.
// Swizzle: 64B rows, 4x16B segs, phys = seg ^ ((row>>1)&3)  (conflict-free).
// ---------------------------------------------------------------------------
#define STAGES 4
#define A_BYTES 16896                 // 264 strip-px * 64 B
#define STAGE_B (A_BYTES + 3 * 8192)  // 41472
#define CONV_SMEM (STAGES * STAGE_B)  // 165888 (>= 131072 epilogue reuse)

__global__ void __launch_bounds__(512, 1)
k_conv(const float* __restrict__ bias, float* __restrict__ out) {
    extern __shared__ __align__(1024) char smem[];
    uint32_t sb = smem_u32(smem);
    float* sbuf = (float*)smem;

    int tid = threadIdx.x, lid = tid & 31, wid = tid >> 5;
    int wm = wid & 3, wn = wid >> 2;              // warp grid 4(M rows) x 4(N)
    int b = blockIdx.x;
    int ocb = b & 1, rq = (b >> 1) & 15, n = b >> 5;
    int y0 = rq * 4, ocBase = ocb * 128;

    const signed char* xqn = g_xq + (size_t)n * PP * PP * Cc;

    int d[4][4][4];
#pragma unroll
    for (int i = 0; i < 4; i++)
#pragma unroll
        for (int j = 0; j < 4; j++)
#pragma unroll
            for (int e = 0; e < 4; e++) d[i][j][e] = 0;

    auto stage = [&](int ch, int s) {
        if (ch < 12) {
            int ky = ch >> 2, icc = ch & 3;
            int ic0 = icc * 64;
            uint32_t As = sb + s * STAGE_B;
            uint32_t Bs = As + A_BYTES;
            // A strip: 264 strip-px (4 rows x 66 cols) x 64 B = 1056 cp16
#pragma unroll
            for (int rr = 0; rr < 3; rr++) {
                int idx = tid + rr * 512;
                if (rr < 2 || tid < 32) {
                    int spx = idx >> 2, c = idx & 3;
                    int r = (spx >= 198) ? 3 : (spx >= 132) ? 2 : (spx >= 66) ? 1 : 0;
                    int col = spx - r * 66;
                    cp16(As + spx * 64 + ((c ^ ((spx >> 1) & 3)) << 4),
                         xqn + ((size_t)(y0 + ky + r) * PP + col) * Cc + ic0 + c * 16);
                }
            }
            // B: 3 kx taps, each 128 oc x 64 B = 512 cp16
#pragma unroll
            for (int t = 0; t < 3; t++) {
                int oc = tid >> 2, c = tid & 3;
                cp16(Bs + t * 8192 + oc * 64 + ((c ^ ((oc >> 1) & 3)) << 4),
                     g_wq + (size_t)(ky * 3 + t) * 65536 + (size_t)(ocBase + oc) * 256
                          + ic0 + c * 16);
            }
        }
        cp_commit();
    };

    stage(0, 0); stage(1, 1); stage(2, 2);

    int sc = 0, sp = 3;                            // consume slot, produce slot
    for (int it = 0; it < 12; it++) {
        __syncthreads();
        stage(it + 3, sp);
        asm volatile("cp.async.wait_group 3;" ::: "memory");
        __syncthreads();

        uint32_t As = sb + sc * STAGE_B;
        uint32_t Bs = As + A_BYTES;
        int grp = lid >> 3, rr = lid & 7;
#pragma unroll
        for (int kx = 0; kx < 3; kx++) {
            uint32_t Bt = Bs + kx * 8192;
#pragma unroll
            for (int h = 0; h < 2; h++) {
                uint32_t a[4][4];
#pragma unroll
                for (int i = 0; i < 4; i++) {
                    int spx = wm * 66 + i * 16 + ((grp & 1) << 3) + rr + kx;
                    int seg = 2 * h + (grp >> 1);
                    ldsm_x4(As + spx * 64 + ((seg ^ ((spx >> 1) & 3)) << 4),
                            a[i][0], a[i][1], a[i][2], a[i][3]);
                }
#pragma unroll
                for (int m = 0; m < 2; m++) {
                    uint32_t bf[4];
                    int ocr = wn * 32 + m * 16 + ((grp >> 1) << 3) + rr;
                    int seg = 2 * h + (grp & 1);
                    ldsm_x4(Bt + ocr * 64 + ((seg ^ ((ocr >> 1) & 3)) << 4),
                            bf[0], bf[1], bf[2], bf[3]);
#pragma unroll
                    for (int i = 0; i < 4; i++) {
                        mma16832(d[i][m * 2], a[i], bf[0], bf[1]);
                        mma16832(d[i][m * 2 + 1], a[i], bf[2], bf[3]);
                    }
                }
            }
        }
        if (++sc == STAGES) sc = 0;
        if (++sp == STAGES) sp = 0;
    }
    asm volatile("cp.async.wait_group 0;" ::: "memory");
    __syncthreads();

    // ---- epilogue: per-warp smem transpose -> coalesced NCHW float4 stores ----
    int wb = wid * 2048;                           // 8KB float region per warp
    int q = lid >> 2, t2 = (lid & 3) * 2;
#pragma unroll
    for (int i = 0; i < 4; i++) {
#pragma unroll
        for (int j = 0; j < 4; j++) {
            int px = i * 16 + q;
            int oc = j * 8 + t2;
            sbuf[wb + oc * 64 + px]           = (float)d[i][j][0];
            sbuf[wb + (oc + 1) * 64 + px]     = (float)d[i][j][1];
            sbuf[wb + oc * 64 + px + 8]       = (float)d[i][j][2];
            sbuf[wb + (oc + 1) * 64 + px + 8] = (float)d[i][j][3];
        }
    }
    __syncwarp();
    float coef = g_coef;
    int y = y0 + wm;
#pragma unroll
    for (int itr = 0; itr < 16; itr++) {
        int ocl = itr * 2 + (lid >> 4);
        int x4 = (lid & 15) * 4;
        float4 v = *(float4*)&sbuf[wb + ocl * 64 + x4];
        int oc = ocBase + wn * 32 + ocl;
        float bz = bias[oc];
        v.x = v.x * coef + bz;
        v.y = v.y * coef + bz;
        v.z = v.z * coef + bz;
        v.w = v.w * coef + bz;
        *(float4*)(out + (((size_t)n * Cc + oc) * Hh + y) * Ww + x4) = v;
    }
}

// ---------------------------------------------------------------------------
// Host launch
// ---------------------------------------------------------------------------
extern "C" void kernel_launch(void* const* d_in, const int* in_sizes, int n_in,
                              void* d_out, int out_size) {
    const float* x    = (const float*)d_in[0];
    const float* w    = (const float*)d_in[1];
    const float* bias = (const float*)d_in[2];
    const float* lnw  = (const float*)d_in[3];
    const float* lnb  = (const float*)d_in[4];
    float* out = (float*)d_out;

    cudaFuncSetAttribute(k_conv, cudaFuncAttributeMaxDynamicSharedMemorySize, CONV_SMEM);

    k_stats<<<dim3(64, Nn), 256>>>(x);
    k_wabs<<<64, 256>>>(w);
    k_post<<<1, 1024>>>(lnw, lnb);
    k_quant_t<<<4096, 256>>>(x, lnw, lnb);
    k_wq_halo<<<2564, 256>>>(w);
    k_conv<<<512, 512, CONV_SMEM>>>(bias, out);
}

// round 12
// speedup vs baseline: 1.5222x; 1.1299x over previous
#include <cuda_runtime.h>
#include <cuda.h>
#include <cuda_bf16.h>
#include <math.h>
#include <stdint.h>

// ---------------------------------------------------------------------------
// Problem constants
// ---------------------------------------------------------------------------
#define Nn   16
#define Cc   256
#define Hh   64
#define Ww   64
#define PP   66                       // padded spatial (1 halo each side)
#define NPIX (Cc*Hh*Ww)               // per-sample elements (GroupNorm group)
#define XQTOT (Nn*PP*PP*Cc)           // NHWC padded int8 activations
#define WTOT (Cc*Cc*9)
#define GN_EPSF 1e-5f

// ---------------------------------------------------------------------------
// Scratch (__device__ globals; no allocation anywhere)
// ---------------------------------------------------------------------------
__device__ __align__(1024) signed char g_xq[XQTOT];   // [n][ph][pw][ic] int8
__device__ __align__(1024) signed char g_wq[WTOT];    // [tap][oc][ic], {-1,0,1}
__device__ double g_spart[Nn*64], g_sspart[Nn*64];    // per-block stat partials
__device__ double g_wpart[64];                        // |w| partials
__device__ float g_cmin[Nn*Cc], g_cmax[Nn*Cc];        // per-(n,c) extremes of x
__device__ float g_meanf[Nn], g_istdf[Nn];
__device__ float g_qscale;   // 128 / gamma
__device__ float g_coef;     // 0.01 * gamma / 128
__device__ float g_delta;    // 0.7 * mean|w|

// ---------------------------------------------------------------------------
// Portable PTX helpers (sm_90-generic or below; no 'a'-suffix features)
// ---------------------------------------------------------------------------
__device__ __forceinline__ uint32_t smem_u32(const void* p) {
    uint32_t a;
    asm("{ .reg .u64 t; cvta.to.shared.u64 t, %1; cvt.u32.u64 %0, t; }" : "=r"(a) : "l"(p));
    return a;
}
__device__ __forceinline__ void ldsm_x4(uint32_t a, uint32_t& r0, uint32_t& r1,
                                        uint32_t& r2, uint32_t& r3) {
    asm volatile("ldmatrix.sync.aligned.m8n8.x4.shared.b16 {%0,%1,%2,%3}, [%4];"
                 : "=r"(r0), "=r"(r1), "=r"(r2), "=r"(r3) : "r"(a));
}
// int8 MMA: D(s32) = A(s8,row) * B(s8,col) + C(s32), 16x8x32
__device__ __forceinline__ void mma16832(int* d, const uint32_t* a,
                                         uint32_t b0, uint32_t b1) {
    asm volatile(
        "mma.sync.aligned.m16n8k32.row.col.s32.s8.s8.s32 "
        "{%0,%1,%2,%3}, {%4,%5,%6,%7}, {%8,%9}, {%0,%1,%2,%3};"
        : "+r"(d[0]), "+r"(d[1]), "+r"(d[2]), "+r"(d[3])
        : "r"(a[0]), "r"(a[1]), "r"(a[2]), "r"(a[3]), "r"(b0), "r"(b1));
}
#define MBAR_INIT(a, cnt) \
    asm volatile("mbarrier.init.shared.b64 [%0], %1;" :: "r"(a), "r"((uint32_t)(cnt)) : "memory")
#define MBAR_EXPECT_TX(a, bytes) \
    asm volatile("mbarrier.arrive.expect_tx.shared.b64 _, [%0], %1;" :: "r"(a), "r"((uint32_t)(bytes)) : "memory")
#define MBAR_WAIT(a, ph) do { \
    uint32_t _m = (a); uint32_t _p = (uint32_t)(ph); \
    asm volatile( \
        "{\n\t.reg .pred P1;\n\t" \
        "WL_%=:\n\t" \
        "mbarrier.try_wait.parity.acquire.cta.shared::cta.b64 P1, [%0], %1, 0x989680;\n\t" \
        "@P1 bra.uni WD_%=;\n\t" \
        "bra.uni WL_%=;\n\t" \
        "WD_%=:\n\t}" \
        :: "r"(_m), "r"(_p) : "memory"); \
} while (0)
#define TMA_LD3D(saddr, tmap, cx, cy, cz, mbar) \
    asm volatile( \
        "cp.async.bulk.tensor.3d.shared::cta.global.tile.mbarrier::complete_tx::bytes " \
        "[%0], [%1, {%2, %3, %4}], [%5];" \
        :: "r"((uint32_t)(saddr)), "l"(tmap), "r"((int32_t)(cx)), "r"((int32_t)(cy)), \
           "r"((int32_t)(cz)), "r"((uint32_t)(mbar)) : "memory")
#define FENCE_ASYNC() asm volatile("fence.proxy.async.shared::cta;" ::: "memory")

// ---------------------------------------------------------------------------
// K1: per-sample sum/sumsq partials + exact per-(n,c) min/max of x.
// Each block covers exactly 4 whole channels (16384 contiguous elems).
// ---------------------------------------------------------------------------
__global__ void k_stats(const float* __restrict__ x) {
    int n = blockIdx.y;
    const float* p = x + (size_t)n * NPIX + (size_t)blockIdx.x * 16384;
    int tid = threadIdx.x;
    float s = 0.f, ss = 0.f;
    float mn[4] = {3.4e38f, 3.4e38f, 3.4e38f, 3.4e38f};
    float mx[4] = {-3.4e38f, -3.4e38f, -3.4e38f, -3.4e38f};
#pragma unroll
    for (int k = 0; k < 16; k++) {
        int ch = k >> 2;
        float4 v = *(const float4*)(p + tid * 4 + k * 1024);
        s  += v.x + v.y + v.z + v.w;
        ss += v.x*v.x + v.y*v.y + v.z*v.z + v.w*v.w;
        mn[ch] = fminf(mn[ch], fminf(fminf(v.x, v.y), fminf(v.z, v.w)));
        mx[ch] = fmaxf(mx[ch], fmaxf(fmaxf(v.x, v.y), fmaxf(v.z, v.w)));
    }
#pragma unroll
    for (int off = 16; off; off >>= 1) {
        s  += __shfl_xor_sync(0xffffffffu, s,  off);
        ss += __shfl_xor_sync(0xffffffffu, ss, off);
#pragma unroll
        for (int j = 0; j < 4; j++) {
            mn[j] = fminf(mn[j], __shfl_xor_sync(0xffffffffu, mn[j], off));
            mx[j] = fmaxf(mx[j], __shfl_xor_sync(0xffffffffu, mx[j], off));
        }
    }
    __shared__ double ws[8], wss[8];
    __shared__ float smn[8][4], smx[8][4];
    int wid = tid >> 5, lane = tid & 31;
    if (lane == 0) {
        ws[wid] = (double)s; wss[wid] = (double)ss;
#pragma unroll
        for (int j = 0; j < 4; j++) { smn[wid][j] = mn[j]; smx[wid][j] = mx[j]; }
    }
    __syncthreads();
    if (tid == 0) {
        double S = 0.0, SS = 0.0;
#pragma unroll
        for (int i = 0; i < 8; i++) { S += ws[i]; SS += wss[i]; }
        g_spart[n * 64 + blockIdx.x] = S;
        g_sspart[n * 64 + blockIdx.x] = SS;
    }
    if (tid < 4) {
        float a = 3.4e38f, bmax = -3.4e38f;
#pragma unroll
        for (int w = 0; w < 8; w++) {
            a = fminf(a, smn[w][tid]);
            bmax = fmaxf(bmax, smx[w][tid]);
        }
        int c = blockIdx.x * 4 + tid;
        g_cmin[n * Cc + c] = a;
        g_cmax[n * Cc + c] = bmax;
    }
}

// ---------------------------------------------------------------------------
// K1w: |w| partials
// ---------------------------------------------------------------------------
__global__ void k_wabs(const float* __restrict__ w) {
    int tid = threadIdx.x;
    float s = 0.f;
    for (int i = blockIdx.x * 256 + tid; i < WTOT; i += gridDim.x * 256)
        s += fabsf(w[i]);
#pragma unroll
    for (int off = 16; off; off >>= 1) s += __shfl_xor_sync(0xffffffffu, s, off);
    __shared__ double ws[8];
    int wid = tid >> 5, lane = tid & 31;
    if (lane == 0) ws[wid] = (double)s;
    __syncthreads();
    if (tid == 0) {
        double S = 0.0;
#pragma unroll
        for (int i = 0; i < 8; i++) S += ws[i];
        g_wpart[blockIdx.x] = S;
    }
}

// ---------------------------------------------------------------------------
// K2: reduce partials, finalize scalars (gamma from per-channel endpoints;
// same fp formula on actual data values -> bit-identical to elementwise max)
// ---------------------------------------------------------------------------
__global__ void k_post(const float* __restrict__ lnw, const float* __restrict__ lnb) {
    __shared__ float sm[Nn], si[Nn];
    __shared__ double swabs;
    __shared__ float wred[32];
    int tid = threadIdx.x;
    if (tid < Nn) {
        double S = 0.0, SS = 0.0;
#pragma unroll
        for (int i = 0; i < 64; i++) {
            S += g_spart[tid * 64 + i];
            SS += g_sspart[tid * 64 + i];
        }
        double mm = S * (1.0 / (double)NPIX);
        double vv = SS * (1.0 / (double)NPIX) - mm * mm;
        float fm = (float)mm;
        float istd = 1.0f / sqrtf((float)vv + GN_EPSF);
        g_meanf[tid] = fm; g_istdf[tid] = istd;
        sm[tid] = fm; si[tid] = istd;
    }
    if (tid == 16) {
        double W = 0.0;
#pragma unroll
        for (int i = 0; i < 64; i++) W += g_wpart[i];
        swabs = W;
    }
    __syncthreads();
    float m = 0.f;
#pragma unroll
    for (int it = 0; it < 4; it++) {
        int idx = it * 1024 + tid;
        int n = idx >> 8, c = idx & 255;
        float fm = sm[n], istd = si[n], g = lnw[c], bb = lnb[c];
        m = fmaxf(m, fabsf(((g_cmin[idx] - fm) * istd) * g + bb));
        m = fmaxf(m, fabsf(((g_cmax[idx] - fm) * istd) * g + bb));
    }
#pragma unroll
    for (int off = 16; off; off >>= 1) m = fmaxf(m, __shfl_xor_sync(0xffffffffu, m, off));
    int wid = tid >> 5, lane = tid & 31;
    if (lane == 0) wred[wid] = m;
    __syncthreads();
    if (tid == 0) {
#pragma unroll
        for (int i = 1; i < 32; i++) m = fmaxf(m, wred[i]);
        float gamma = fmaxf(m, 1e-6f);
        g_qscale = 128.0f / gamma;
        g_coef = 0.01f * gamma * (1.0f / 128.0f);
        g_delta = 0.7f * (float)(swabs * (1.0 / (double)WTOT));
    }
}

// ---------------------------------------------------------------------------
// K3: quantize + NCHW->NHWC transpose, int8 register transpose via byte_perm.
// Block handles 64 ch x 64 px.  Phase 1: quantize in registers, 4x4 byte
// transpose, 32-bit stores into XOR-swizzled int8 smem tile [px][72B rows].
// Phase 2: uint2 reads -> coalesced NHWC stores.
// ---------------------------------------------------------------------------
__global__ void k_quant_t(const float* __restrict__ x,
                          const float* __restrict__ lnw,
                          const float* __restrict__ lnb) {
    __shared__ __align__(16) signed char s8[64 * 72];
    int b = blockIdx.x;
    int ic4 = b & 3, h = (b >> 2) & 63, n = b >> 8;
    int tid = threadIdx.x;
    float mean = g_meanf[n], istd = g_istdf[n], qs = g_qscale;

    const float* xb = x + ((size_t)n * Cc + ic4 * 64) * 4096 + h * 64;
    int px4 = tid & 15, cg = tid >> 4;

    uint32_t w[4];
#pragma unroll
    for (int k = 0; k < 4; k++) {
        int ch = cg * 4 + k;
        int c = ic4 * 64 + ch;
        float g = lnw[c], bb = lnb[c];
        float4 v = *(const float4*)(xb + (size_t)ch * 4096 + px4 * 4);
        float f[4] = {v.x, v.y, v.z, v.w};
        uint32_t pk = 0;
#pragma unroll
        for (int e = 0; e < 4; e++) {
            float xl = ((f[e] - mean) * istd) * g + bb;
            float z = fminf(fmaxf(xl * qs, -128.0f), 128.0f);
            int qi = (int)rintf(z);
            if (qi > 127) qi = 127;                 // int8 clamp (+128 -> 127)
            pk |= (uint32_t)(qi & 255) << (8 * e);
        }
        w[k] = pk;
    }
    // 4x4 byte transpose: o[e] = channels cg*4..+3 for px = px4*4+e
    uint32_t lo01 = __byte_perm(w[0], w[1], 0x5140);
    uint32_t hi01 = __byte_perm(w[0], w[1], 0x7362);
    uint32_t lo23 = __byte_perm(w[2], w[3], 0x5140);
    uint32_t hi23 = __byte_perm(w[2], w[3], 0x7362);
    uint32_t o0 = __byte_perm(lo01, lo23, 0x5410);
    uint32_t o1 = __byte_perm(lo01, lo23, 0x7632);
    uint32_t o2 = __byte_perm(hi01, hi23, 0x5410);
    uint32_t o3 = __byte_perm(hi01, hi23, 0x7632);
    // store at [px][ (cg ^ px4) * 4 ], row stride 72 B
    {
        int cs = (cg ^ px4) << 2;
        int base = (px4 * 4) * 72 + cs;
        *(uint32_t*)&s8[base]           = o0;
        *(uint32_t*)&s8[base + 72]      = o1;
        *(uint32_t*)&s8[base + 144]     = o2;
        *(uint32_t*)&s8[base + 216]     = o3;
    }
    __syncthreads();

    signed char* ob = g_xq + ((size_t)(n * PP + h + 1) * PP + 1) * Cc + ic4 * 64;
#pragma unroll
    for (int pass = 0; pass < 2; pass++) {
        int j = tid + pass * 256;                   // 0..511
        int p = j >> 3, s = j & 7;
        int p4 = p >> 2;
        int pp = s ^ (p4 >> 1);                     // phys pair
        uint2 u = *(uint2*)&s8[p * 72 + pp * 8];
        if (p4 & 1) { uint32_t t = u.x; u.x = u.y; u.y = t; }
        *(uint2*)(ob + (size_t)p * Cc + s * 8) = u;
    }
}

// ---------------------------------------------------------------------------
// K3w: ternarize weights -> int8 [tap][oc][ic]  +  halo zeroing (merged)
// blocks [0,2304): weights;  blocks [2304,2564): halo
// ---------------------------------------------------------------------------
__global__ void k_wq_halo(const float* __restrict__ w) {
    int bx = blockIdx.x;
    int tid = threadIdx.x;
    if (bx < 2304) {
        int idx = bx * 256 + tid;
        int tap = idx >> 16;
        int rem = idx & 65535;
        int oc = rem >> 8, ic = rem & 255;
        float v = w[(size_t)(oc * Cc + ic) * 9 + tap];
        float d = g_delta;
        g_wq[idx] = (v > d) ? 1 : ((v < -d) ? -1 : 0);
    } else {
        int idx = (bx - 2304) * 256 + tid;          // 260 blocks
        int n = idx / (260 * 16);
        int r = idx - n * (260 * 16);
        int p = r >> 4, q = r & 15;
        int ph, pw;
        if (p < 66)       { ph = 0;       pw = p; }
        else if (p < 132) { ph = 65;      pw = p - 66; }
        else if (p < 196) { ph = p - 131; pw = 0; }
        else              { ph = p - 195; pw = 65; }
        uint4 z = make_uint4(0, 0, 0, 0);
        *(uint4*)(g_xq + ((size_t)(n * PP + ph) * PP + pw) * Cc + q * 16) = z;
    }
}

// ---------------------------------------------------------------------------
// K4: int8 implicit-GEMM conv, TMA-staged.
// CTA = 256 px (4 rows) x 128 oc, 512 threads, 16 warps 4(M) x 4(N).
// 12 chunks = ky(3) x 64-ic chunk(4).  Per chunk: ONE TMA A load (box
// {64ic, 66pw, 4rows} = 16896 B) + ONE TMA B load (box {64ic, 128oc, 3taps}
// = 24576 B), mbarrier expect_tx 41472.
// TMA SWIZZLE_64B == consumer XOR (seg ^ ((row>>1)&3)) — consumer unchanged.
// ---------------------------------------------------------------------------
#define STAGES 4
#define A_BYTES 16896                 // 4 x 66 x 64
#define B_BYTES 24576                 // 3 x 128 x 64
#define CHUNK_BYTES (A_BYTES + B_BYTES)
#define STAGE_B 41984                 // padded to 1024
#define CONV_SMEM (1024 + STAGES * STAGE_B)   // 168960

__global__ void __launch_bounds__(512, 1)
k_conv(const __grid_constant__ CUtensorMap mapA,
       const __grid_constant__ CUtensorMap mapB,
       const float* __restrict__ bias, float* __restrict__ out) {
    extern __shared__ __align__(1024) char smem[];
    uint32_t sb = smem_u32(smem);
    uint32_t sb0 = sb + 1024;                      // stage ring base
    float* sbuf = (float*)smem;

    int tid = threadIdx.x, lid = tid & 31, wid = tid >> 5;
    int wm = wid & 3, wn = wid >> 2;               // warp grid 4(M rows) x 4(N)
    int b = blockIdx.x;
    int ocb = b & 1, rq = (b >> 1) & 15, n = b >> 5;
    int y0 = rq * 4, ocBase = ocb * 128;

    if (tid == 0) {
#pragma unroll
        for (int s = 0; s < STAGES; s++) MBAR_INIT(sb + 8 * s, 1);
        FENCE_ASYNC();
    }
    __syncthreads();

    int d[4][4][4];
#pragma unroll
    for (int i = 0; i < 4; i++)
#pragma unroll
        for (int j = 0; j < 4; j++)
#pragma unroll
            for (int e = 0; e < 4; e++) d[i][j][e] = 0;

    auto issue = [&](int ch) {
        int s = ch & 3;
        int ky = ch >> 2, icc = ch & 3;
        int ic0 = icc * 64;
        uint32_t dst = sb0 + s * STAGE_B;
        uint32_t mb = sb + 8 * s;
        MBAR_EXPECT_TX(mb, CHUNK_BYTES);
        TMA_LD3D(dst, &mapA, ic0, 0, n * PP + y0 + ky, mb);
        TMA_LD3D(dst + A_BYTES, &mapB, ic0, ocBase, ky * 3, mb);
    };

    if (tid == 0) { issue(0); issue(1); issue(2); }

    for (int it = 0; it < 12; it++) {
        __syncthreads();                            // prior slot consumption done
        if (tid == 0 && it + 3 < 12) issue(it + 3);
        MBAR_WAIT(sb + 8 * (it & 3), (it >> 2) & 1);

        uint32_t As = sb0 + (it & 3) * STAGE_B;
        uint32_t Bs = As + A_BYTES;
        int grp = lid >> 3, rr = lid & 7;
#pragma unroll
        for (int kx = 0; kx < 3; kx++) {
            uint32_t Bt = Bs + kx * 8192;
#pragma unroll
            for (int h = 0; h < 2; h++) {
                uint32_t a[4][4];
#pragma unroll
                for (int i = 0; i < 4; i++) {
                    int spx = wm * 66 + i * 16 + ((grp & 1) << 3) + rr + kx;
                    int seg = 2 * h + (grp >> 1);
                    ldsm_x4(As + spx * 64 + ((seg ^ ((spx >> 1) & 3)) << 4),
                            a[i][0], a[i][1], a[i][2], a[i][3]);
                }
#pragma unroll
                for (int m = 0; m < 2; m++) {
                    uint32_t bf[4];
                    int ocr = wn * 32 + m * 16 + ((grp >> 1) << 3) + rr;
                    int seg = 2 * h + (grp & 1);
                    ldsm_x4(Bt + ocr * 64 + ((seg ^ ((ocr >> 1) & 3)) << 4),
                            bf[0], bf[1], bf[2], bf[3]);
#pragma unroll
                    for (int i = 0; i < 4; i++) {
                        mma16832(d[i][m * 2], a[i], bf[0], bf[1]);
                        mma16832(d[i][m * 2 + 1], a[i], bf[2], bf[3]);
                    }
                }
            }
        }
    }
    __syncthreads();                                // all consumption finished

    // ---- epilogue: per-warp smem transpose -> coalesced NCHW float4 stores ----
    int wb = 256 + wid * 2048;                      // skip mbarrier area
    int q = lid >> 2, t2 = (lid & 3) * 2;
#pragma unroll
    for (int i = 0; i < 4; i++) {
#pragma unroll
        for (int j = 0; j < 4; j++) {
            int px = i * 16 + q;
            int oc = j * 8 + t2;
            sbuf[wb + oc * 64 + px]           = (float)d[i][j][0];
            sbuf[wb + (oc + 1) * 64 + px]     = (float)d[i][j][1];
            sbuf[wb + oc * 64 + px + 8]       = (float)d[i][j][2];
            sbuf[wb + (oc + 1) * 64 + px + 8] = (float)d[i][j][3];
        }
    }
    __syncwarp();
    float coef = g_coef;
    int y = y0 + wm;
#pragma unroll
    for (int itr = 0; itr < 16; itr++) {
        int ocl = itr * 2 + (lid >> 4);
        int x4 = (lid & 15) * 4;
        float4 v = *(float4*)&sbuf[wb + ocl * 64 + x4];
        int oc = ocBase + wn * 32 + ocl;
        float bz = bias[oc];
        v.x = v.x * coef + bz;
        v.y = v.y * coef + bz;
        v.z = v.z * coef + bz;
        v.w = v.w * coef + bz;
        *(float4*)(out + (((size_t)n * Cc + oc) * Hh + y) * Ww + x4) = v;
    }
}

// ---------------------------------------------------------------------------
// Host launch
// ---------------------------------------------------------------------------
typedef CUresult (*PFN_encode)(CUtensorMap*, CUtensorMapDataType, cuuint32_t, void*,
                               const cuuint64_t*, const cuuint64_t*, const cuuint32_t*,
                               const cuuint32_t*, CUtensorMapInterleave, CUtensorMapSwizzle,
                               CUtensorMapL2promotion, CUtensorMapFloatOOBfill);

extern "C" void kernel_launch(void* const* d_in, const int* in_sizes, int n_in,
                              void* d_out, int out_size) {
    const float* x    = (const float*)d_in[0];
    const float* w    = (const float*)d_in[1];
    const float* bias = (const float*)d_in[2];
    const float* lnw  = (const float*)d_in[3];
    const float* lnb  = (const float*)d_in[4];
    float* out = (float*)d_out;

    void* fn = nullptr;
    cudaDriverEntryPointQueryResult qr;
    cudaGetDriverEntryPointByVersion("cuTensorMapEncodeTiled", &fn, 12000,
                                     cudaEnableDefault, &qr);
    PFN_encode enc = (PFN_encode)fn;

    void *xq_ptr = nullptr, *wq_ptr = nullptr;
    cudaGetSymbolAddress(&xq_ptr, g_xq);
    cudaGetSymbolAddress(&wq_ptr, g_wq);

    CUtensorMap mapA, mapB;
    {   // activations: [ic=256, pw=66, n*ph=1056], box {64,66,4}, SW64
        cuuint64_t dims[3]    = {256, 66, (cuuint64_t)(Nn * PP)};
        cuuint64_t strides[2] = {256, 66 * 256};
        cuuint32_t box[3]     = {64, 66, 4};
        cuuint32_t es[3]      = {1, 1, 1};
        enc(&mapA, CU_TENSOR_MAP_DATA_TYPE_UINT8, 3, xq_ptr, dims, strides, box, es,
            CU_TENSOR_MAP_INTERLEAVE_NONE, CU_TENSOR_MAP_SWIZZLE_64B,
            CU_TENSOR_MAP_L2_PROMOTION_L2_128B, CU_TENSOR_MAP_FLOAT_OOB_FILL_NONE);
    }
    {   // weights: [ic=256, oc=256, tap=9], box {64,128,3}, SW64
        cuuint64_t dims[3]    = {256, 256, 9};
        cuuint64_t strides[2] = {256, 65536};
        cuuint32_t box[3]     = {64, 128, 3};
        cuuint32_t es[3]      = {1, 1, 1};
        enc(&mapB, CU_TENSOR_MAP_DATA_TYPE_UINT8, 3, wq_ptr, dims, strides, box, es,
            CU_TENSOR_MAP_INTERLEAVE_NONE, CU_TENSOR_MAP_SWIZZLE_64B,
            CU_TENSOR_MAP_L2_PROMOTION_L2_128B, CU_TENSOR_MAP_FLOAT_OOB_FILL_NONE);
    }

    cudaFuncSetAttribute(k_conv, cudaFuncAttributeMaxDynamicSharedMemorySize, CONV_SMEM);

    k_stats<<<dim3(64, Nn), 256>>>(x);
    k_wabs<<<64, 256>>>(w);
    k_post<<<1, 1024>>>(lnw, lnb);
    k_quant_t<<<4096, 256>>>(x, lnw, lnb);
    k_wq_halo<<<2564, 256>>>(w);
    k_conv<<<512, 512, CONV_SMEM>>>(mapA, mapB, bias, out);
}

// round 14
// speedup vs baseline: 1.6914x; 1.1111x over previous
#include <cuda_runtime.h>
#include <cuda.h>
#include <cuda_bf16.h>
#include <math.h>
#include <stdint.h>

// ---------------------------------------------------------------------------
// Problem constants
// ---------------------------------------------------------------------------
#define Nn   16
#define Cc   256
#define Hh   64
#define Ww   64
#define PP   66                       // padded spatial (1 halo each side)
#define NPIX (Cc*Hh*Ww)               // per-sample elements (GroupNorm group)
#define XQTOT (Nn*PP*PP*Cc)           // NHWC padded int8 activations
#define WTOT (Cc*Cc*9)
#define GN_EPSF 1e-5f

// ---------------------------------------------------------------------------
// Scratch (__device__ globals; no allocation anywhere)
// ---------------------------------------------------------------------------
__device__ __align__(1024) signed char g_xq[XQTOT];   // [n][ph][pw][ic] int8
__device__ __align__(1024) signed char g_wq[WTOT];    // [tap][oc][ic], {-1,0,1}
__device__ double g_spart[Nn*64], g_sspart[Nn*64];    // per-block stat partials
__device__ double g_wpart[8];                         // |w| partials
__device__ float g_cmin[Nn*Cc], g_cmax[Nn*Cc];        // per-(n,c) extremes of x
__device__ float g_meanf[Nn], g_istdf[Nn];
__device__ float g_qscale;   // 128 / gamma
__device__ float g_coef;     // 0.01 * gamma / 128
__device__ float g_delta;    // 0.7 * mean|w|

// ---------------------------------------------------------------------------
// Portable PTX helpers (sm_90-generic or below; no 'a'-suffix features)
// ---------------------------------------------------------------------------
__device__ __forceinline__ uint32_t smem_u32(const void* p) {
    uint32_t a;
    asm("{ .reg .u64 t; cvta.to.shared.u64 t, %1; cvt.u32.u64 %0, t; }" : "=r"(a) : "l"(p));
    return a;
}
__device__ __forceinline__ void ldsm_x4(uint32_t a, uint32_t& r0, uint32_t& r1,
                                        uint32_t& r2, uint32_t& r3) {
    asm volatile("ldmatrix.sync.aligned.m8n8.x4.shared.b16 {%0,%1,%2,%3}, [%4];"
                 : "=r"(r0), "=r"(r1), "=r"(r2), "=r"(r3) : "r"(a));
}
// int8 MMA: D(s32) = A(s8,row) * B(s8,col) + C(s32), 16x8x32
__device__ __forceinline__ void mma16832(int* d, const uint32_t* a,
                                         uint32_t b0, uint32_t b1) {
    asm volatile(
        "mma.sync.aligned.m16n8k32.row.col.s32.s8.s8.s32 "
        "{%0,%1,%2,%3}, {%4,%5,%6,%7}, {%8,%9}, {%0,%1,%2,%3};"
        : "+r"(d[0]), "+r"(d[1]), "+r"(d[2]), "+r"(d[3])
        : "r"(a[0]), "r"(a[1]), "r"(a[2]), "r"(a[3]), "r"(b0), "r"(b1));
}
#define MBAR_INIT(a, cnt) \
    asm volatile("mbarrier.init.shared.b64 [%0], %1;" :: "r"(a), "r"((uint32_t)(cnt)) : "memory")
#define MBAR_EXPECT_TX(a, bytes) \
    asm volatile("mbarrier.arrive.expect_tx.shared.b64 _, [%0], %1;" :: "r"(a), "r"((uint32_t)(bytes)) : "memory")
#define MBAR_WAIT(a, ph) do { \
    uint32_t _m = (a); uint32_t _p = (uint32_t)(ph); \
    asm volatile( \
        "{\n\t.reg .pred P1;\n\t" \
        "WL_%=:\n\t" \
        "mbarrier.try_wait.parity.acquire.cta.shared::cta.b64 P1, [%0], %1, 0x989680;\n\t" \
        "@P1 bra.uni WD_%=;\n\t" \
        "bra.uni WL_%=;\n\t" \
        "WD_%=:\n\t}" \
        :: "r"(_m), "r"(_p) : "memory"); \
} while (0)
#define TMA_LD3D(saddr, tmap, cx, cy, cz, mbar) \
    asm volatile( \
        "cp.async.bulk.tensor.3d.shared::cta.global.tile.mbarrier::complete_tx::bytes " \
        "[%0], [%1, {%2, %3, %4}], [%5];" \
        :: "r"((uint32_t)(saddr)), "l"(tmap), "r"((int32_t)(cx)), "r"((int32_t)(cy)), \
           "r"((int32_t)(cz)), "r"((uint32_t)(mbar)) : "memory")
#define FENCE_ASYNC() asm volatile("fence.proxy.async.shared::cta;" ::: "memory")

// ---------------------------------------------------------------------------
// K1: per-sample sum/sumsq partials + per-(n,c) min/max of x  (x-blocks 0..63)
//     + |w| partials (x-blocks 64..71, y==0 only) -- merged for overlap.
// ---------------------------------------------------------------------------
__global__ void k_stats(const float* __restrict__ x, const float* __restrict__ w) {
    if (blockIdx.x >= 64) {
        if (blockIdx.y != 0) return;
        int bw = blockIdx.x - 64;                   // 0..7
        int tid = threadIdx.x;
        float s = 0.f;
        for (int i = bw * 256 + tid; i < WTOT; i += 8 * 256)
            s += fabsf(w[i]);
#pragma unroll
        for (int off = 16; off; off >>= 1) s += __shfl_xor_sync(0xffffffffu, s, off);
        __shared__ double ws[8];
        int wid = tid >> 5, lane = tid & 31;
        if (lane == 0) ws[wid] = (double)s;
        __syncthreads();
        if (tid == 0) {
            double S = 0.0;
#pragma unroll
            for (int i = 0; i < 8; i++) S += ws[i];
            g_wpart[bw] = S;
        }
        return;
    }
    int n = blockIdx.y;
    const float* p = x + (size_t)n * NPIX + (size_t)blockIdx.x * 16384;
    int tid = threadIdx.x;
    float s = 0.f, ss = 0.f;
    float mn[4] = {3.4e38f, 3.4e38f, 3.4e38f, 3.4e38f};
    float mx[4] = {-3.4e38f, -3.4e38f, -3.4e38f, -3.4e38f};
#pragma unroll
    for (int k = 0; k < 16; k++) {
        int ch = k >> 2;
        float4 v = *(const float4*)(p + tid * 4 + k * 1024);
        s  += v.x + v.y + v.z + v.w;
        ss += v.x*v.x + v.y*v.y + v.z*v.z + v.w*v.w;
        mn[ch] = fminf(mn[ch], fminf(fminf(v.x, v.y), fminf(v.z, v.w)));
        mx[ch] = fmaxf(mx[ch], fmaxf(fmaxf(v.x, v.y), fmaxf(v.z, v.w)));
    }
#pragma unroll
    for (int off = 16; off; off >>= 1) {
        s  += __shfl_xor_sync(0xffffffffu, s,  off);
        ss += __shfl_xor_sync(0xffffffffu, ss, off);
#pragma unroll
        for (int j = 0; j < 4; j++) {
            mn[j] = fminf(mn[j], __shfl_xor_sync(0xffffffffu, mn[j], off));
            mx[j] = fmaxf(mx[j], __shfl_xor_sync(0xffffffffu, mx[j], off));
        }
    }
    __shared__ double ws[8], wss[8];
    __shared__ float smn[8][4], smx[8][4];
    int wid = tid >> 5, lane = tid & 31;
    if (lane == 0) {
        ws[wid] = (double)s; wss[wid] = (double)ss;
#pragma unroll
        for (int j = 0; j < 4; j++) { smn[wid][j] = mn[j]; smx[wid][j] = mx[j]; }
    }
    __syncthreads();
    if (tid == 0) {
        double S = 0.0, SS = 0.0;
#pragma unroll
        for (int i = 0; i < 8; i++) { S += ws[i]; SS += wss[i]; }
        g_spart[n * 64 + blockIdx.x] = S;
        g_sspart[n * 64 + blockIdx.x] = SS;
    }
    if (tid < 4) {
        float a = 3.4e38f, bmax = -3.4e38f;
#pragma unroll
        for (int w2 = 0; w2 < 8; w2++) {
            a = fminf(a, smn[w2][tid]);
            bmax = fmaxf(bmax, smx[w2][tid]);
        }
        int c = blockIdx.x * 4 + tid;
        g_cmin[n * Cc + c] = a;
        g_cmax[n * Cc + c] = bmax;
    }
}

// ---------------------------------------------------------------------------
// K2: reduce partials, finalize scalars (gamma from per-channel endpoints;
// same fp formula on actual data values -> bit-identical to elementwise max)
// ---------------------------------------------------------------------------
__global__ void k_post(const float* __restrict__ lnw, const float* __restrict__ lnb) {
    __shared__ float sm[Nn], si[Nn];
    __shared__ double swabs;
    __shared__ float wred[32];
    int tid = threadIdx.x;
    if (tid < Nn) {
        double S = 0.0, SS = 0.0;
#pragma unroll
        for (int i = 0; i < 64; i++) {
            S += g_spart[tid * 64 + i];
            SS += g_sspart[tid * 64 + i];
        }
        double mm = S * (1.0 / (double)NPIX);
        double vv = SS * (1.0 / (double)NPIX) - mm * mm;
        float fm = (float)mm;
        float istd = 1.0f / sqrtf((float)vv + GN_EPSF);
        g_meanf[tid] = fm; g_istdf[tid] = istd;
        sm[tid] = fm; si[tid] = istd;
    }
    if (tid == 16) {
        double W = 0.0;
#pragma unroll
        for (int i = 0; i < 8; i++) W += g_wpart[i];
        swabs = W;
    }
    __syncthreads();
    float m = 0.f;
#pragma unroll
    for (int it = 0; it < 4; it++) {
        int idx = it * 1024 + tid;
        int n = idx >> 8, c = idx & 255;
        float fm = sm[n], istd = si[n], g = lnw[c], bb = lnb[c];
        m = fmaxf(m, fabsf(((g_cmin[idx] - fm) * istd) * g + bb));
        m = fmaxf(m, fabsf(((g_cmax[idx] - fm) * istd) * g + bb));
    }
#pragma unroll
    for (int off = 16; off; off >>= 1) m = fmaxf(m, __shfl_xor_sync(0xffffffffu, m, off));
    int wid = tid >> 5, lane = tid & 31;
    if (lane == 0) wred[wid] = m;
    __syncthreads();
    if (tid == 0) {
#pragma unroll
        for (int i = 1; i < 32; i++) m = fmaxf(m, wred[i]);
        float gamma = fmaxf(m, 1e-6f);
        g_qscale = 128.0f / gamma;
        g_coef = 0.01f * gamma * (1.0f / 128.0f);
        g_delta = 0.7f * (float)(swabs * (1.0 / (double)WTOT));
    }
}

// ---------------------------------------------------------------------------
// K3 (merged): blocks [0,4096): quantize+transpose activations;
//              blocks [4096,6400): ternarize weights;
//              blocks [6400,6660): zero halo.
// Quant path: per-channel FFMA (t = istd*lnw*qs, cq = lnb*qs - mean*t),
// 4x4 byte_perm register transpose, XOR-swizzled int8 smem, uint2 stores.
// ---------------------------------------------------------------------------
__global__ void k_prep(const float* __restrict__ x, const float* __restrict__ w,
                       const float* __restrict__ lnw, const float* __restrict__ lnb) {
    int bx = blockIdx.x;
    int tid = threadIdx.x;
    if (bx >= 4096) {
        if (bx < 6400) {
            int idx = (bx - 4096) * 256 + tid;
            int tap = idx >> 16;
            int rem = idx & 65535;
            int oc = rem >> 8, ic = rem & 255;
            float v = w[(size_t)(oc * Cc + ic) * 9 + tap];
            float d = g_delta;
            g_wq[idx] = (v > d) ? 1 : ((v < -d) ? -1 : 0);
        } else {
            int idx = (bx - 6400) * 256 + tid;      // 260 blocks
            int n = idx / (260 * 16);
            int r = idx - n * (260 * 16);
            int p = r >> 4, q = r & 15;
            int ph, pw;
            if (p < 66)       { ph = 0;       pw = p; }
            else if (p < 132) { ph = 65;      pw = p - 66; }
            else if (p < 196) { ph = p - 131; pw = 0; }
            else              { ph = p - 195; pw = 65; }
            uint4 z = make_uint4(0, 0, 0, 0);
            *(uint4*)(g_xq + ((size_t)(n * PP + ph) * PP + pw) * Cc + q * 16) = z;
        }
        return;
    }

    __shared__ __align__(16) signed char s8[64 * 72];
    int ic4 = bx & 3, h = (bx >> 2) & 63, n = bx >> 8;
    float mean = g_meanf[n], istd = g_istdf[n], qs = g_qscale;

    const float* xb = x + ((size_t)n * Cc + ic4 * 64) * 4096 + h * 64;
    int px4 = tid & 15, cg = tid >> 4;

    uint32_t wv[4];
#pragma unroll
    for (int k = 0; k < 4; k++) {
        int ch = cg * 4 + k;
        int c = ic4 * 64 + ch;
        float t = istd * lnw[c] * qs;               // per-channel scale
        float cq = fmaf(-mean, t, lnb[c] * qs);     // per-channel offset
        float4 v = *(const float4*)(xb + (size_t)ch * 4096 + px4 * 4);
        float f[4] = {v.x, v.y, v.z, v.w};
        uint32_t pk = 0;
#pragma unroll
        for (int e = 0; e < 4; e++) {
            float z = fmaf(f[e], t, cq);
            z = fminf(fmaxf(z, -128.0f), 128.0f);
            int qi = (int)rintf(z);
            if (qi > 127) qi = 127;                 // int8 clamp (+128 -> 127)
            pk |= (uint32_t)(qi & 255) << (8 * e);
        }
        wv[k] = pk;
    }
    // 4x4 byte transpose
    uint32_t lo01 = __byte_perm(wv[0], wv[1], 0x5140);
    uint32_t hi01 = __byte_perm(wv[0], wv[1], 0x7362);
    uint32_t lo23 = __byte_perm(wv[2], wv[3], 0x5140);
    uint32_t hi23 = __byte_perm(wv[2], wv[3], 0x7362);
    uint32_t o0 = __byte_perm(lo01, lo23, 0x5410);
    uint32_t o1 = __byte_perm(lo01, lo23, 0x7632);
    uint32_t o2 = __byte_perm(hi01, hi23, 0x5410);
    uint32_t o3 = __byte_perm(hi01, hi23, 0x7632);
    {
        int cs = (cg ^ px4) << 2;
        int base = (px4 * 4) * 72 + cs;
        *(uint32_t*)&s8[base]           = o0;
        *(uint32_t*)&s8[base + 72]      = o1;
        *(uint32_t*)&s8[base + 144]     = o2;
        *(uint32_t*)&s8[base + 216]     = o3;
    }
    __syncthreads();

    signed char* ob = g_xq + ((size_t)(n * PP + h + 1) * PP + 1) * Cc + ic4 * 64;
#pragma unroll
    for (int pass = 0; pass < 2; pass++) {
        int j = tid + pass * 256;                   // 0..511
        int p = j >> 3, s = j & 7;
        int p4 = p >> 2;
        int pp = s ^ (p4 >> 1);
        uint2 u = *(uint2*)&s8[p * 72 + pp * 8];
        if (p4 & 1) { uint32_t t = u.x; u.x = u.y; u.y = t; }
        *(uint2*)(ob + (size_t)p * Cc + s * 8) = u;
    }
}

// ---------------------------------------------------------------------------
// K4: int8 implicit-GEMM conv, TMA-staged (unchanged from R12 WIN).
// CTA = 256 px (4 rows) x 128 oc, 512 threads, 16 warps 4(M) x 4(N).
// 12 chunks = ky(3) x 64-ic chunk(4); one TMA A box {64,66,4} + one TMA B
// box {64,128,3} per chunk; SWIZZLE_64B == consumer XOR.
// ---------------------------------------------------------------------------
#define STAGES 4
#define A_BYTES 16896                 // 4 x 66 x 64
#define B_BYTES 24576                 // 3 x 128 x 64
#define CHUNK_BYTES (A_BYTES + B_BYTES)
#define STAGE_B 41984                 // padded to 1024
#define CONV_SMEM (1024 + STAGES * STAGE_B)   // 168960

__global__ void __launch_bounds__(512, 1)
k_conv(const __grid_constant__ CUtensorMap mapA,
       const __grid_constant__ CUtensorMap mapB,
       const float* __restrict__ bias, float* __restrict__ out) {
    extern __shared__ __align__(1024) char smem[];
    uint32_t sb = smem_u32(smem);
    uint32_t sb0 = sb + 1024;
    float* sbuf = (float*)smem;

    int tid = threadIdx.x, lid = tid & 31, wid = tid >> 5;
    int wm = wid & 3, wn = wid >> 2;
    int b = blockIdx.x;
    int ocb = b & 1, rq = (b >> 1) & 15, n = b >> 5;
    int y0 = rq * 4, ocBase = ocb * 128;

    if (tid == 0) {
#pragma unroll
        for (int s = 0; s < STAGES; s++) MBAR_INIT(sb + 8 * s, 1);
        FENCE_ASYNC();
    }
    __syncthreads();

    int d[4][4][4];
#pragma unroll
    for (int i = 0; i < 4; i++)
#pragma unroll
        for (int j = 0; j < 4; j++)
#pragma unroll
            for (int e = 0; e < 4; e++) d[i][j][e] = 0;

    auto issue = [&](int ch) {
        int s = ch & 3;
        int ky = ch >> 2, icc = ch & 3;
        int ic0 = icc * 64;
        uint32_t dst = sb0 + s * STAGE_B;
        uint32_t mb = sb + 8 * s;
        MBAR_EXPECT_TX(mb, CHUNK_BYTES);
        TMA_LD3D(dst, &mapA, ic0, 0, n * PP + y0 + ky, mb);
        TMA_LD3D(dst + A_BYTES, &mapB, ic0, ocBase, ky * 3, mb);
    };

    if (tid == 0) { issue(0); issue(1); issue(2); }

    for (int it = 0; it < 12; it++) {
        __syncthreads();
        if (tid == 0 && it + 3 < 12) issue(it + 3);
        MBAR_WAIT(sb + 8 * (it & 3), (it >> 2) & 1);

        uint32_t As = sb0 + (it & 3) * STAGE_B;
        uint32_t Bs = As + A_BYTES;
        int grp = lid >> 3, rr = lid & 7;
#pragma unroll
        for (int kx = 0; kx < 3; kx++) {
            uint32_t Bt = Bs + kx * 8192;
#pragma unroll
            for (int h = 0; h < 2; h++) {
                uint32_t a[4][4];
#pragma unroll
                for (int i = 0; i < 4; i++) {
                    int spx = wm * 66 + i * 16 + ((grp & 1) << 3) + rr + kx;
                    int seg = 2 * h + (grp >> 1);
                    ldsm_x4(As + spx * 64 + ((seg ^ ((spx >> 1) & 3)) << 4),
                            a[i][0], a[i][1], a[i][2], a[i][3]);
                }
#pragma unroll
                for (int m = 0; m < 2; m++) {
                    uint32_t bf[4];
                    int ocr = wn * 32 + m * 16 + ((grp >> 1) << 3) + rr;
                    int seg = 2 * h + (grp & 1);
                    ldsm_x4(Bt + ocr * 64 + ((seg ^ ((ocr >> 1) & 3)) << 4),
                            bf[0], bf[1], bf[2], bf[3]);
#pragma unroll
                    for (int i = 0; i < 4; i++) {
                        mma16832(d[i][m * 2], a[i], bf[0], bf[1]);
                        mma16832(d[i][m * 2 + 1], a[i], bf[2], bf[3]);
                    }
                }
            }
        }
    }
    __syncthreads();

    // ---- epilogue: per-warp smem transpose -> coalesced NCHW float4 stores ----
    int wb = 256 + wid * 2048;
    int q = lid >> 2, t2 = (lid & 3) * 2;
#pragma unroll
    for (int i = 0; i < 4; i++) {
#pragma unroll
        for (int j = 0; j < 4; j++) {
            int px = i * 16 + q;
            int oc = j * 8 + t2;
            sbuf[wb + oc * 64 + px]           = (float)d[i][j][0];
            sbuf[wb + (oc + 1) * 64 + px]     = (float)d[i][j][1];
            sbuf[wb + oc * 64 + px + 8]       = (float)d[i][j][2];
            sbuf[wb + (oc + 1) * 64 + px + 8] = (float)d[i][j][3];
        }
    }
    __syncwarp();
    float coef = g_coef;
    int y = y0 + wm;
#pragma unroll
    for (int itr = 0; itr < 16; itr++) {
        int ocl = itr * 2 + (lid >> 4);
        int x4 = (lid & 15) * 4;
        float4 v = *(float4*)&sbuf[wb + ocl * 64 + x4];
        int oc = ocBase + wn * 32 + ocl;
        float bz = bias[oc];
        v.x = v.x * coef + bz;
        v.y = v.y * coef + bz;
        v.z = v.z * coef + bz;
        v.w = v.w * coef + bz;
        *(float4*)(out + (((size_t)n * Cc + oc) * Hh + y) * Ww + x4) = v;
    }
}

// ---------------------------------------------------------------------------
// Host launch
// ---------------------------------------------------------------------------
typedef CUresult (*PFN_encode)(CUtensorMap*, CUtensorMapDataType, cuuint32_t, void*,
                               const cuuint64_t*, const cuuint64_t*, const cuuint32_t*,
                               const cuuint32_t*, CUtensorMapInterleave, CUtensorMapSwizzle,
                               CUtensorMapL2promotion, CUtensorMapFloatOOBfill);

extern "C" void kernel_launch(void* const* d_in, const int* in_sizes, int n_in,
                              void* d_out, int out_size) {
    const float* x    = (const float*)d_in[0];
    const float* w    = (const float*)d_in[1];
    const float* bias = (const float*)d_in[2];
    const float* lnw  = (const float*)d_in[3];
    const float* lnb  = (const float*)d_in[4];
    float* out = (float*)d_out;

    void* fn = nullptr;
    cudaDriverEntryPointQueryResult qr;
    cudaGetDriverEntryPointByVersion("cuTensorMapEncodeTiled", &fn, 12000,
                                     cudaEnableDefault, &qr);
    PFN_encode enc = (PFN_encode)fn;

    void *xq_ptr = nullptr, *wq_ptr = nullptr;
    cudaGetSymbolAddress(&xq_ptr, g_xq);
    cudaGetSymbolAddress(&wq_ptr, g_wq);

    CUtensorMap mapA, mapB;
    {   // activations: [ic=256, pw=66, n*ph=1056], box {64,66,4}, SW64
        cuuint64_t dims[3]    = {256, 66, (cuuint64_t)(Nn * PP)};
        cuuint64_t strides[2] = {256, 66 * 256};
        cuuint32_t box[3]     = {64, 66, 4};
        cuuint32_t es[3]      = {1, 1, 1};
        enc(&mapA, CU_TENSOR_MAP_DATA_TYPE_UINT8, 3, xq_ptr, dims, strides, box, es,
            CU_TENSOR_MAP_INTERLEAVE_NONE, CU_TENSOR_MAP_SWIZZLE_64B,
            CU_TENSOR_MAP_L2_PROMOTION_L2_128B, CU_TENSOR_MAP_FLOAT_OOB_FILL_NONE);
    }
    {   // weights: [ic=256, oc=256, tap=9], box {64,128,3}, SW64
        cuuint64_t dims[3]    = {256, 256, 9};
        cuuint64_t strides[2] = {256, 65536};
        cuuint32_t box[3]     = {64, 128, 3};
        cuuint32_t es[3]      = {1, 1, 1};
        enc(&mapB, CU_TENSOR_MAP_DATA_TYPE_UINT8, 3, wq_ptr, dims, strides, box, es,
            CU_TENSOR_MAP_INTERLEAVE_NONE, CU_TENSOR_MAP_SWIZZLE_64B,
            CU_TENSOR_MAP_L2_PROMOTION_L2_128B, CU_TENSOR_MAP_FLOAT_OOB_FILL_NONE);
    }

    cudaFuncSetAttribute(k_conv, cudaFuncAttributeMaxDynamicSharedMemorySize, CONV_SMEM);

    k_stats<<<dim3(72, Nn), 256>>>(x, w);
    k_post<<<1, 1024>>>(lnw, lnb);
    k_prep<<<6660, 256>>>(x, w, lnw, lnb);
    k_conv<<<512, 512, CONV_SMEM>>>(mapA, mapB, bias, out);
}

// round 15
// speedup vs baseline: 1.8440x; 1.0902x over previous
#include <cuda_runtime.h>
#include <cuda.h>
#include <cuda_bf16.h>
#include <math.h>
#include <stdint.h>

// ---------------------------------------------------------------------------
// Problem constants
// ---------------------------------------------------------------------------
#define Nn   16
#define Cc   256
#define Hh   64
#define Ww   64
#define PP   66                       // padded spatial (1 halo each side)
#define NPIX (Cc*Hh*Ww)               // per-sample elements (GroupNorm group)
#define XQTOT (Nn*PP*PP*Cc)           // NHWC padded int8 activations
#define WTOT (Cc*Cc*9)
#define GN_EPSF 1e-5f
#define NTILES 512
#define GRIDP 148

// ---------------------------------------------------------------------------
// Scratch (__device__ globals; no allocation anywhere)
// ---------------------------------------------------------------------------
__device__ __align__(1024) signed char g_xq[XQTOT];   // [n][ph][pw][ic] int8
__device__ __align__(1024) signed char g_wq[WTOT];    // [tap][oc][ic], {-1,0,1}
__device__ double g_spart[Nn*64], g_sspart[Nn*64];    // per-block stat partials
__device__ double g_wpart[8];                         // |w| partials
__device__ float g_cmin[Nn*Cc], g_cmax[Nn*Cc];        // per-(n,c) extremes of x
__device__ float g_meanf[Nn], g_istdf[Nn];
__device__ float g_qscale;   // 128 / gamma
__device__ float g_coef;     // 0.01 * gamma / 128
__device__ float g_delta;    // 0.7 * mean|w|

// ---------------------------------------------------------------------------
// Portable PTX helpers (sm_90-generic or below; no 'a'-suffix features)
// ---------------------------------------------------------------------------
__device__ __forceinline__ uint32_t smem_u32(const void* p) {
    uint32_t a;
    asm("{ .reg .u64 t; cvta.to.shared.u64 t, %1; cvt.u32.u64 %0, t; }" : "=r"(a) : "l"(p));
    return a;
}
__device__ __forceinline__ void ldsm_x4(uint32_t a, uint32_t& r0, uint32_t& r1,
                                        uint32_t& r2, uint32_t& r3) {
    asm volatile("ldmatrix.sync.aligned.m8n8.x4.shared.b16 {%0,%1,%2,%3}, [%4];"
                 : "=r"(r0), "=r"(r1), "=r"(r2), "=r"(r3) : "r"(a));
}
// int8 MMA: D(s32) = A(s8,row) * B(s8,col) + C(s32), 16x8x32
__device__ __forceinline__ void mma16832(int* d, const uint32_t* a,
                                         uint32_t b0, uint32_t b1) {
    asm volatile(
        "mma.sync.aligned.m16n8k32.row.col.s32.s8.s8.s32 "
        "{%0,%1,%2,%3}, {%4,%5,%6,%7}, {%8,%9}, {%0,%1,%2,%3};"
        : "+r"(d[0]), "+r"(d[1]), "+r"(d[2]), "+r"(d[3])
        : "r"(a[0]), "r"(a[1]), "r"(a[2]), "r"(a[3]), "r"(b0), "r"(b1));
}
#define MBAR_INIT(a, cnt) \
    asm volatile("mbarrier.init.shared.b64 [%0], %1;" :: "r"(a), "r"((uint32_t)(cnt)) : "memory")
#define MBAR_EXPECT_TX(a, bytes) \
    asm volatile("mbarrier.arrive.expect_tx.shared.b64 _, [%0], %1;" :: "r"(a), "r"((uint32_t)(bytes)) : "memory")
#define MBAR_WAIT(a, ph) do { \
    uint32_t _m = (a); uint32_t _p = (uint32_t)(ph); \
    asm volatile( \
        "{\n\t.reg .pred P1;\n\t" \
        "WL_%=:\n\t" \
        "mbarrier.try_wait.parity.acquire.cta.shared::cta.b64 P1, [%0], %1, 0x989680;\n\t" \
        "@P1 bra.uni WD_%=;\n\t" \
        "bra.uni WL_%=;\n\t" \
        "WD_%=:\n\t}" \
        :: "r"(_m), "r"(_p) : "memory"); \
} while (0)
#define TMA_LD3D(saddr, tmap, cx, cy, cz, mbar) \
    asm volatile( \
        "cp.async.bulk.tensor.3d.shared::cta.global.tile.mbarrier::complete_tx::bytes " \
        "[%0], [%1, {%2, %3, %4}], [%5];" \
        :: "r"((uint32_t)(saddr)), "l"(tmap), "r"((int32_t)(cx)), "r"((int32_t)(cy)), \
           "r"((int32_t)(cz)), "r"((uint32_t)(mbar)) : "memory")
#define FENCE_ASYNC() asm volatile("fence.proxy.async.shared::cta;" ::: "memory")

// ---------------------------------------------------------------------------
// K1: per-sample sum/sumsq partials + per-(n,c) min/max of x  (x-blocks 0..63)
//     + |w| partials (x-blocks 64..71, y==0 only) -- merged for overlap.
// ---------------------------------------------------------------------------
__global__ void k_stats(const float* __restrict__ x, const float* __restrict__ w) {
    if (blockIdx.x >= 64) {
        if (blockIdx.y != 0) return;
        int bw = blockIdx.x - 64;                   // 0..7
        int tid = threadIdx.x;
        float s = 0.f;
        for (int i = bw * 256 + tid; i < WTOT; i += 8 * 256)
            s += fabsf(w[i]);
#pragma unroll
        for (int off = 16; off; off >>= 1) s += __shfl_xor_sync(0xffffffffu, s, off);
        __shared__ double ws[8];
        int wid = tid >> 5, lane = tid & 31;
        if (lane == 0) ws[wid] = (double)s;
        __syncthreads();
        if (tid == 0) {
            double S = 0.0;
#pragma unroll
            for (int i = 0; i < 8; i++) S += ws[i];
            g_wpart[bw] = S;
        }
        return;
    }
    int n = blockIdx.y;
    const float* p = x + (size_t)n * NPIX + (size_t)blockIdx.x * 16384;
    int tid = threadIdx.x;
    float s = 0.f, ss = 0.f;
    float mn[4] = {3.4e38f, 3.4e38f, 3.4e38f, 3.4e38f};
    float mx[4] = {-3.4e38f, -3.4e38f, -3.4e38f, -3.4e38f};
#pragma unroll
    for (int k = 0; k < 16; k++) {
        int ch = k >> 2;
        float4 v = *(const float4*)(p + tid * 4 + k * 1024);
        s  += v.x + v.y + v.z + v.w;
        ss += v.x*v.x + v.y*v.y + v.z*v.z + v.w*v.w;
        mn[ch] = fminf(mn[ch], fminf(fminf(v.x, v.y), fminf(v.z, v.w)));
        mx[ch] = fmaxf(mx[ch], fmaxf(fmaxf(v.x, v.y), fmaxf(v.z, v.w)));
    }
#pragma unroll
    for (int off = 16; off; off >>= 1) {
        s  += __shfl_xor_sync(0xffffffffu, s,  off);
        ss += __shfl_xor_sync(0xffffffffu, ss, off);
#pragma unroll
        for (int j = 0; j < 4; j++) {
            mn[j] = fminf(mn[j], __shfl_xor_sync(0xffffffffu, mn[j], off));
            mx[j] = fmaxf(mx[j], __shfl_xor_sync(0xffffffffu, mx[j], off));
        }
    }
    __shared__ double ws[8], wss[8];
    __shared__ float smn[8][4], smx[8][4];
    int wid = tid >> 5, lane = tid & 31;
    if (lane == 0) {
        ws[wid] = (double)s; wss[wid] = (double)ss;
#pragma unroll
        for (int j = 0; j < 4; j++) { smn[wid][j] = mn[j]; smx[wid][j] = mx[j]; }
    }
    __syncthreads();
    if (tid == 0) {
        double S = 0.0, SS = 0.0;
#pragma unroll
        for (int i = 0; i < 8; i++) { S += ws[i]; SS += wss[i]; }
        g_spart[n * 64 + blockIdx.x] = S;
        g_sspart[n * 64 + blockIdx.x] = SS;
    }
    if (tid < 4) {
        float a = 3.4e38f, bmax = -3.4e38f;
#pragma unroll
        for (int w2 = 0; w2 < 8; w2++) {
            a = fminf(a, smn[w2][tid]);
            bmax = fmaxf(bmax, smx[w2][tid]);
        }
        int c = blockIdx.x * 4 + tid;
        g_cmin[n * Cc + c] = a;
        g_cmax[n * Cc + c] = bmax;
    }
}

// ---------------------------------------------------------------------------
// K2: reduce partials, finalize scalars (gamma from per-channel endpoints;
// same fp formula on actual data values -> bit-identical to elementwise max)
// ---------------------------------------------------------------------------
__global__ void k_post(const float* __restrict__ lnw, const float* __restrict__ lnb) {
    __shared__ float sm[Nn], si[Nn];
    __shared__ double swabs;
    __shared__ float wred[32];
    int tid = threadIdx.x;
    if (tid < Nn) {
        double S = 0.0, SS = 0.0;
#pragma unroll
        for (int i = 0; i < 64; i++) {
            S += g_spart[tid * 64 + i];
            SS += g_sspart[tid * 64 + i];
        }
        double mm = S * (1.0 / (double)NPIX);
        double vv = SS * (1.0 / (double)NPIX) - mm * mm;
        float fm = (float)mm;
        float istd = 1.0f / sqrtf((float)vv + GN_EPSF);
        g_meanf[tid] = fm; g_istdf[tid] = istd;
        sm[tid] = fm; si[tid] = istd;
    }
    if (tid == 16) {
        double W = 0.0;
#pragma unroll
        for (int i = 0; i < 8; i++) W += g_wpart[i];
        swabs = W;
    }
    __syncthreads();
    float m = 0.f;
#pragma unroll
    for (int it = 0; it < 4; it++) {
        int idx = it * 1024 + tid;
        int n = idx >> 8, c = idx & 255;
        float fm = sm[n], istd = si[n], g = lnw[c], bb = lnb[c];
        m = fmaxf(m, fabsf(((g_cmin[idx] - fm) * istd) * g + bb));
        m = fmaxf(m, fabsf(((g_cmax[idx] - fm) * istd) * g + bb));
    }
#pragma unroll
    for (int off = 16; off; off >>= 1) m = fmaxf(m, __shfl_xor_sync(0xffffffffu, m, off));
    int wid = tid >> 5, lane = tid & 31;
    if (lane == 0) wred[wid] = m;
    __syncthreads();
    if (tid == 0) {
#pragma unroll
        for (int i = 1; i < 32; i++) m = fmaxf(m, wred[i]);
        float gamma = fmaxf(m, 1e-6f);
        g_qscale = 128.0f / gamma;
        g_coef = 0.01f * gamma * (1.0f / 128.0f);
        g_delta = 0.7f * (float)(swabs * (1.0 / (double)WTOT));
    }
}

// ---------------------------------------------------------------------------
// K3 (merged): blocks [0,4096): quantize+transpose activations;
//              blocks [4096,6400): ternarize weights;
//              blocks [6400,6660): zero halo.
// ---------------------------------------------------------------------------
__global__ void k_prep(const float* __restrict__ x, const float* __restrict__ w,
                       const float* __restrict__ lnw, const float* __restrict__ lnb) {
    int bx = blockIdx.x;
    int tid = threadIdx.x;
    if (bx >= 4096) {
        if (bx < 6400) {
            int idx = (bx - 4096) * 256 + tid;
            int tap = idx >> 16;
            int rem = idx & 65535;
            int oc = rem >> 8, ic = rem & 255;
            float v = w[(size_t)(oc * Cc + ic) * 9 + tap];
            float d = g_delta;
            g_wq[idx] = (v > d) ? 1 : ((v < -d) ? -1 : 0);
        } else {
            int idx = (bx - 6400) * 256 + tid;      // 260 blocks
            int n = idx / (260 * 16);
            int r = idx - n * (260 * 16);
            int p = r >> 4, q = r & 15;
            int ph, pw;
            if (p < 66)       { ph = 0;       pw = p; }
            else if (p < 132) { ph = 65;      pw = p - 66; }
            else if (p < 196) { ph = p - 131; pw = 0; }
            else              { ph = p - 195; pw = 65; }
            uint4 z = make_uint4(0, 0, 0, 0);
            *(uint4*)(g_xq + ((size_t)(n * PP + ph) * PP + pw) * Cc + q * 16) = z;
        }
        return;
    }

    __shared__ __align__(16) signed char s8[64 * 72];
    int ic4 = bx & 3, h = (bx >> 2) & 63, n = bx >> 8;
    float mean = g_meanf[n], istd = g_istdf[n], qs = g_qscale;

    const float* xb = x + ((size_t)n * Cc + ic4 * 64) * 4096 + h * 64;
    int px4 = tid & 15, cg = tid >> 4;

    uint32_t wv[4];
#pragma unroll
    for (int k = 0; k < 4; k++) {
        int ch = cg * 4 + k;
        int c = ic4 * 64 + ch;
        float t = istd * lnw[c] * qs;               // per-channel scale
        float cq = fmaf(-mean, t, lnb[c] * qs);     // per-channel offset
        float4 v = *(const float4*)(xb + (size_t)ch * 4096 + px4 * 4);
        float f[4] = {v.x, v.y, v.z, v.w};
        uint32_t pk = 0;
#pragma unroll
        for (int e = 0; e < 4; e++) {
            float z = fmaf(f[e], t, cq);
            z = fminf(fmaxf(z, -128.0f), 128.0f);
            int qi = (int)rintf(z);
            if (qi > 127) qi = 127;                 // int8 clamp (+128 -> 127)
            pk |= (uint32_t)(qi & 255) << (8 * e);
        }
        wv[k] = pk;
    }
    uint32_t lo01 = __byte_perm(wv[0], wv[1], 0x5140);
    uint32_t hi01 = __byte_perm(wv[0], wv[1], 0x7362);
    uint32_t lo23 = __byte_perm(wv[2], wv[3], 0x5140);
    uint32_t hi23 = __byte_perm(wv[2], wv[3], 0x7362);
    uint32_t o0 = __byte_perm(lo01, lo23, 0x5410);
    uint32_t o1 = __byte_perm(lo01, lo23, 0x7632);
    uint32_t o2 = __byte_perm(hi01, hi23, 0x5410);
    uint32_t o3 = __byte_perm(hi01, hi23, 0x7632);
    {
        int cs = (cg ^ px4) << 2;
        int base = (px4 * 4) * 72 + cs;
        *(uint32_t*)&s8[base]           = o0;
        *(uint32_t*)&s8[base + 72]      = o1;
        *(uint32_t*)&s8[base + 144]     = o2;
        *(uint32_t*)&s8[base + 216]     = o3;
    }
    __syncthreads();

    signed char* ob = g_xq + ((size_t)(n * PP + h + 1) * PP + 1) * Cc + ic4 * 64;
#pragma unroll
    for (int pass = 0; pass < 2; pass++) {
        int j = tid + pass * 256;                   // 0..511
        int p = j >> 3, s = j & 7;
        int p4 = p >> 2;
        int pp = s ^ (p4 >> 1);
        uint2 u = *(uint2*)&s8[p * 72 + pp * 8];
        if (p4 & 1) { uint32_t t = u.x; u.x = u.y; u.y = t; }
        *(uint2*)(ob + (size_t)p * Cc + s * 8) = u;
    }
}

// ---------------------------------------------------------------------------
// K4: PERSISTENT int8 implicit-GEMM conv, TMA-staged.
// grid = 148 CTAs; CTA c processes tiles c, c+148, ... (3-4 tiles) as ONE
// continuous chunk stream through a 4-slot ring (no per-tile drain).
// Tile = 256 px (4 rows) x 128 oc; 12 chunks/tile (ky x 64-ic).
// Epilogue: direct register->gmem scalar stores (no smem reuse; hazard-free).
// ---------------------------------------------------------------------------
#define STAGES 4
#define A_BYTES 16896                 // 4 x 66 x 64
#define B_BYTES 24576                 // 3 x 128 x 64
#define CHUNK_BYTES (A_BYTES + B_BYTES)
#define STAGE_B 41984                 // padded to 1024
#define CONV_SMEM (1024 + STAGES * STAGE_B)   // 168960

__global__ void __launch_bounds__(512, 1)
k_conv(const __grid_constant__ CUtensorMap mapA,
       const __grid_constant__ CUtensorMap mapB,
       const float* __restrict__ bias, float* __restrict__ out) {
    extern __shared__ __align__(1024) char smem[];
    uint32_t sb = smem_u32(smem);
    uint32_t sb0 = sb + 1024;

    int tid = threadIdx.x, lid = tid & 31, wid = tid >> 5;
    int wm = wid & 3, wn = wid >> 2;               // warp grid 4(M rows) x 4(N)
    int bx = blockIdx.x;

    int nTiles = (NTILES - 1 - bx) / GRIDP + 1;    // 3 or 4
    int totc = nTiles * 12;

    if (tid == 0) {
#pragma unroll
        for (int s = 0; s < STAGES; s++) MBAR_INIT(sb + 8 * s, 1);
        FENCE_ASYNC();
    }
    __syncthreads();

    int d[4][4][4];
#pragma unroll
    for (int i = 0; i < 4; i++)
#pragma unroll
        for (int j = 0; j < 4; j++)
#pragma unroll
            for (int e = 0; e < 4; e++) d[i][j][e] = 0;

    // issue chunk c (global within this CTA's stream)
    auto issue = [&](int c) {
        int s = c & 3;
        int k = c / 12, within = c - k * 12;
        int b = bx + k * GRIDP;                     // tile id
        int ocb = b & 1, rq = (b >> 1) & 15, n = b >> 5;
        int ky = within >> 2, icc = within & 3;
        int ic0 = icc * 64;
        uint32_t dst = sb0 + s * STAGE_B;
        uint32_t mb = sb + 8 * s;
        MBAR_EXPECT_TX(mb, CHUNK_BYTES);
        TMA_LD3D(dst, &mapA, ic0, 0, n * PP + rq * 4 + ky, mb);
        TMA_LD3D(dst + A_BYTES, &mapB, ic0, ocb * 128, ky * 3, mb);
    };

    if (tid == 0) { issue(0); issue(1); issue(2); }

    float coef = g_coef;
    int grp = lid >> 3, rr = lid & 7;
    int q = lid >> 2, t2 = (lid & 3) * 2;

    for (int c = 0; c < totc; c++) {
        __syncthreads();                            // slot (c+3)&3's old use done
        if (tid == 0 && c + 3 < totc) issue(c + 3);
        MBAR_WAIT(sb + 8 * (c & 3), (c >> 2) & 1);

        uint32_t As = sb0 + (c & 3) * STAGE_B;
        uint32_t Bs = As + A_BYTES;
#pragma unroll
        for (int kx = 0; kx < 3; kx++) {
            uint32_t Bt = Bs + kx * 8192;
#pragma unroll
            for (int h = 0; h < 2; h++) {
                uint32_t a[4][4];
#pragma unroll
                for (int i = 0; i < 4; i++) {
                    int spx = wm * 66 + i * 16 + ((grp & 1) << 3) + rr + kx;
                    int seg = 2 * h + (grp >> 1);
                    ldsm_x4(As + spx * 64 + ((seg ^ ((spx >> 1) & 3)) << 4),
                            a[i][0], a[i][1], a[i][2], a[i][3]);
                }
#pragma unroll
                for (int m = 0; m < 2; m++) {
                    uint32_t bf[4];
                    int ocr = wn * 32 + m * 16 + ((grp >> 1) << 3) + rr;
                    int seg = 2 * h + (grp & 1);
                    ldsm_x4(Bt + ocr * 64 + ((seg ^ ((ocr >> 1) & 3)) << 4),
                            bf[0], bf[1], bf[2], bf[3]);
#pragma unroll
                    for (int i = 0; i < 4; i++) {
                        mma16832(d[i][m * 2], a[i], bf[0], bf[1]);
                        mma16832(d[i][m * 2 + 1], a[i], bf[2], bf[3]);
                    }
                }
            }
        }

        // ---- tile finished? direct register epilogue, then reset accums ----
        if (c % 12 == 11) {
            int k = c / 12;
            int b = bx + k * GRIDP;
            int ocb = b & 1, rq = (b >> 1) & 15, n = b >> 5;
            int y = rq * 4 + wm;
            float* ob = out + ((size_t)n * Cc) * 4096 + (size_t)y * 64;
#pragma unroll
            for (int j = 0; j < 4; j++) {
#pragma unroll
                for (int e2 = 0; e2 < 2; e2++) {    // e&1: oc parity
                    int oc = ocb * 128 + wn * 32 + j * 8 + t2 + e2;
                    float bz = bias[oc];
                    float* oo = ob + (size_t)oc * 4096;
#pragma unroll
                    for (int i = 0; i < 4; i++) {
                        oo[i * 16 + q]     = (float)d[i][j][e2] * coef + bz;
                        oo[i * 16 + q + 8] = (float)d[i][j][e2 + 2] * coef + bz;
                    }
                }
            }
#pragma unroll
            for (int i = 0; i < 4; i++)
#pragma unroll
                for (int j = 0; j < 4; j++)
#pragma unroll
                    for (int e = 0; e < 4; e++) d[i][j][e] = 0;
        }
    }
}

// ---------------------------------------------------------------------------
// Host launch
// ---------------------------------------------------------------------------
typedef CUresult (*PFN_encode)(CUtensorMap*, CUtensorMapDataType, cuuint32_t, void*,
                               const cuuint64_t*, const cuuint64_t*, const cuuint32_t*,
                               const cuuint32_t*, CUtensorMapInterleave, CUtensorMapSwizzle,
                               CUtensorMapL2promotion, CUtensorMapFloatOOBfill);

extern "C" void kernel_launch(void* const* d_in, const int* in_sizes, int n_in,
                              void* d_out, int out_size) {
    const float* x    = (const float*)d_in[0];
    const float* w    = (const float*)d_in[1];
    const float* bias = (const float*)d_in[2];
    const float* lnw  = (const float*)d_in[3];
    const float* lnb  = (const float*)d_in[4];
    float* out = (float*)d_out;

    void* fn = nullptr;
    cudaDriverEntryPointQueryResult qr;
    cudaGetDriverEntryPointByVersion("cuTensorMapEncodeTiled", &fn, 12000,
                                     cudaEnableDefault, &qr);
    PFN_encode enc = (PFN_encode)fn;

    void *xq_ptr = nullptr, *wq_ptr = nullptr;
    cudaGetSymbolAddress(&xq_ptr, g_xq);
    cudaGetSymbolAddress(&wq_ptr, g_wq);

    CUtensorMap mapA, mapB;
    {   // activations: [ic=256, pw=66, n*ph=1056], box {64,66,4}, SW64
        cuuint64_t dims[3]    = {256, 66, (cuuint64_t)(Nn * PP)};
        cuuint64_t strides[2] = {256, 66 * 256};
        cuuint32_t box[3]     = {64, 66, 4};
        cuuint32_t es[3]      = {1, 1, 1};
        enc(&mapA, CU_TENSOR_MAP_DATA_TYPE_UINT8, 3, xq_ptr, dims, strides, box, es,
            CU_TENSOR_MAP_INTERLEAVE_NONE, CU_TENSOR_MAP_SWIZZLE_64B,
            CU_TENSOR_MAP_L2_PROMOTION_L2_128B, CU_TENSOR_MAP_FLOAT_OOB_FILL_NONE);
    }
    {   // weights: [ic=256, oc=256, tap=9], box {64,128,3}, SW64
        cuuint64_t dims[3]    = {256, 256, 9};
        cuuint64_t strides[2] = {256, 65536};
        cuuint32_t box[3]     = {64, 128, 3};
        cuuint32_t es[3]      = {1, 1, 1};
        enc(&mapB, CU_TENSOR_MAP_DATA_TYPE_UINT8, 3, wq_ptr, dims, strides, box, es,
            CU_TENSOR_MAP_INTERLEAVE_NONE, CU_TENSOR_MAP_SWIZZLE_64B,
            CU_TENSOR_MAP_L2_PROMOTION_L2_128B, CU_TENSOR_MAP_FLOAT_OOB_FILL_NONE);
    }

    cudaFuncSetAttribute(k_conv, cudaFuncAttributeMaxDynamicSharedMemorySize, CONV_SMEM);

    k_stats<<<dim3(72, Nn), 256>>>(x, w);
    k_post<<<1, 1024>>>(lnw, lnb);
    k_prep<<<6660, 256>>>(x, w, lnw, lnb);
    k_conv<<<GRIDP, 512, CONV_SMEM>>>(mapA, mapB, bias, out);
}